// round 5
// baseline (speedup 1.0000x reference)
#include <cuda_runtime.h>
#include <cuda_fp16.h>
#include <math.h>
#include <stdint.h>

#define N_NODES 3000
#define IN_DIM  512
#define HID     64
#define HEADS   8
#define CAT     512      // HEADS*HID
#define NCLASS  16
#define MAXDEG  256
#define ALPHA   0.2f

// ---------------- scratch (static device globals; no allocation) -------------
__device__ float  g_dinv[N_NODES];
__device__ int    g_cnt [N_NODES];
__device__ int    g_cols[N_NODES * MAXDEG];
__device__ float  g_wv  [N_NODES * MAXDEG];     // raw a1 (adj + I) values
__device__ float  g_Wc  [IN_DIM * CAT];         // packed W_heads -> [k][head*64+f]
__device__ float  g_H   [N_NODES * CAT];        // fp32 h, [i][head*64+f]
__device__ __half g_Hh  [N_NODES * CAT];        // fp16 copy for attn1 gather
__device__ float  g_srcT[N_NODES * HEADS];      // [node][head]
__device__ float  g_dstT[N_NODES * HEADS];
__device__ float  g_X1  [N_NODES * CAT];
__device__ float  g_H2  [N_NODES * NCLASS];
__device__ float  g_s2  [N_NODES];
__device__ float  g_d2  [N_NODES];
__device__ float  g_Z   [N_NODES * NCLASS];

__device__ __forceinline__ float elu1(float x) { return x > 0.f ? x : expm1f(x); }
__device__ __forceinline__ float lrelu(float x){ return x >= 0.f ? x : ALPHA * x; }

// ---------------- 1. pack W_heads [8][512][64] -> Wc [512][512] --------------
__global__ void pack_w(const float* __restrict__ W_heads) {
    int k = blockIdx.x;
    int c = threadIdx.x;
    g_Wc[k * CAT + c] = W_heads[(c >> 6) * (IN_DIM * HID) + k * HID + (c & 63)];
}

// ---------------- 2. edge build: 4 warps/row, column-segment partition -------
#define SEGQ 188
__global__ __launch_bounds__(128) void build_edges(const float* __restrict__ adj) {
    int row  = blockIdx.x;
    int tid  = threadIdx.x;
    int w    = tid >> 5, lane = tid & 31;
    __shared__ int   s_bufc[4][128];
    __shared__ float s_bufv[4][128];
    __shared__ int   s_cnt[4];
    __shared__ float s_sum[4];

    const float4* arow4 = (const float4*)(adj + (size_t)row * N_NODES);
    const int NQ = N_NODES / 4;
    int q0 = w * SEGQ;
    int q1 = min(q0 + SEGQ, NQ);

    int cnt = 0;
    float rsum = 0.f;
    for (int base = q0; base < q1; base += 32) {
        int q = base + lane;
        bool valid = q < q1;
        float a[4] = {0.f, 0.f, 0.f, 0.f};
        int j0 = q * 4;
        if (valid) {
            float4 v = arow4[q];
            a[0] = v.x; a[1] = v.y; a[2] = v.z; a[3] = v.w;
            if (row >= j0 && row < j0 + 4) a[row - j0] += 1.f;   // +I
        }
        rsum += a[0] + a[1] + a[2] + a[3];
#pragma unroll
        for (int t = 0; t < 4; t++) {
            bool has = valid && (a[t] > 0.f);
            unsigned msk = __ballot_sync(0xffffffffu, has);
            if (has) {
                int pos = cnt + __popc(msk & ((1u << lane) - 1u));
                if (pos < 128) {
                    s_bufc[w][pos] = j0 + t;
                    s_bufv[w][pos] = a[t];
                }
            }
            cnt += __popc(msk);
        }
    }
#pragma unroll
    for (int o = 16; o; o >>= 1) rsum += __shfl_xor_sync(0xffffffffu, rsum, o);
    if (lane == 0) { s_cnt[w] = cnt; s_sum[w] = rsum; }
    __syncthreads();

    int c0 = 0;
#pragma unroll
    for (int t = 0; t < 4; t++) if (t < w) c0 += s_cnt[t];
    int myc = min(s_cnt[w], 128);
    for (int k = lane; k < myc; k += 32) {
        int pos = c0 + k;
        if (pos < MAXDEG) {
            g_cols[row * MAXDEG + pos] = s_bufc[w][k];
            g_wv [row * MAXDEG + pos] = s_bufv[w][k];
        }
    }
    if (tid == 0) {
        int tot = s_cnt[0] + s_cnt[1] + s_cnt[2] + s_cnt[3];
        g_cnt[row]  = tot < MAXDEG ? tot : MAXDEG;
        g_dinv[row] = rsqrtf(s_sum[0] + s_sum[1] + s_sum[2] + s_sum[3]);
    }
}

// ---------------- 3. H = X @ Wc : 64x64 tiles, 256 thr, 4x4 microtile --------
#define BM 64
#define BN 64
#define BK 16
__global__ __launch_bounds__(256) void sgemm_H(const float* __restrict__ A) {
    __shared__ float As[2][BK][BM];
    __shared__ float Bs[2][BK][BN];
    int tid = threadIdx.x;
    int warp = tid >> 5, lane = tid & 31;
    int wr = (warp & 3) * 16, wc = (warp >> 2) * 32;   // warp tile 16x32
    int lr = lane >> 3, lc = lane & 7;                 // 4x8 lanes, 4x4 each
    int brow = blockIdx.y * BM, bcol = blockIdx.x * BN;

    int ar = tid >> 2, akk = (tid & 3) * 4;            // A: row, k-quad
    int brr = tid >> 4, bcc = (tid & 15) * 4;          // B: k-row, col-quad
    const float* Aptr = A + (size_t)(brow + ar) * IN_DIM + akk;
    bool aok = (brow + ar) < N_NODES;
    const float* Bptr = g_Wc + (size_t)brr * CAT + bcol + bcc;
    const float4 z4 = make_float4(0.f, 0.f, 0.f, 0.f);

    float4 ra = aok ? *(const float4*)(Aptr) : z4;
    float4 rb = *(const float4*)(Bptr);
    As[0][akk + 0][ar] = ra.x; As[0][akk + 1][ar] = ra.y;
    As[0][akk + 2][ar] = ra.z; As[0][akk + 3][ar] = ra.w;
    *(float4*)&Bs[0][brr][bcc] = rb;
    __syncthreads();

    float acc[4][4] = {};
    int cur = 0;
    for (int k0 = BK; k0 <= IN_DIM; k0 += BK) {
        bool last = (k0 == IN_DIM);
        if (!last) {
            ra = aok ? *(const float4*)(Aptr + k0) : z4;
            rb = *(const float4*)(Bptr + (size_t)k0 * CAT);
        }
        // software-pipelined fragments
        float4 xa = *(float4*)&As[cur][0][wr + lr * 4];
        float4 yb = *(float4*)&Bs[cur][0][wc + lc * 4];
#pragma unroll
        for (int k = 0; k < BK; k++) {
            float4 xn = xa, yn = yb;
            if (k + 1 < BK) {
                xn = *(float4*)&As[cur][k + 1][wr + lr * 4];
                yn = *(float4*)&Bs[cur][k + 1][wc + lc * 4];
            }
            float xv[4] = {xa.x, xa.y, xa.z, xa.w};
            float yv[4] = {yb.x, yb.y, yb.z, yb.w};
#pragma unroll
            for (int i = 0; i < 4; i++)
#pragma unroll
                for (int j = 0; j < 4; j++)
                    acc[i][j] = fmaf(xv[i], yv[j], acc[i][j]);
            xa = xn; yb = yn;
        }
        if (!last) {
            int nxt = cur ^ 1;
            As[nxt][akk + 0][ar] = ra.x; As[nxt][akk + 1][ar] = ra.y;
            As[nxt][akk + 2][ar] = ra.z; As[nxt][akk + 3][ar] = ra.w;
            *(float4*)&Bs[nxt][brr][bcc] = rb;
        }
        __syncthreads();
        cur ^= 1;
    }
#pragma unroll
    for (int i = 0; i < 4; i++) {
        int row = brow + wr + lr * 4 + i;
        if (row < N_NODES) {
            int col = bcol + wc + lc * 4;
            float4 o = make_float4(acc[i][0], acc[i][1], acc[i][2], acc[i][3]);
            *(float4*)(g_H + (size_t)row * CAT + col) = o;
            __half2 h0 = __floats2half2_rn(o.x, o.y);
            __half2 h1 = __floats2half2_rn(o.z, o.w);
            __half2* hp = (__half2*)(g_Hh + (size_t)row * CAT + col);
            hp[0] = h0; hp[1] = h1;
        }
    }
}

// ---------------- 4. src/dst per head -> [node][head] ------------------------
__global__ void srcdst1(const float* __restrict__ a_heads) {
    int i = blockIdx.x;
    int head = threadIdx.x >> 5, lane = threadIdx.x & 31;
    const float* h = g_H + (size_t)i * CAT + head * HID;
    const float* a = a_heads + head * (2 * HID);
    float h0 = h[lane], h1 = h[lane + 32];
    float s = h0 * a[lane]      + h1 * a[lane + 32];
    float d = h0 * a[64 + lane] + h1 * a[96 + lane];
#pragma unroll
    for (int o = 16; o; o >>= 1) {
        s += __shfl_xor_sync(0xffffffffu, s, o);
        d += __shfl_xor_sync(0xffffffffu, d, o);
    }
    if (lane == 0) {
        g_srcT[i * HEADS + head] = s;
        g_dstT[i * HEADS + head] = d;
    }
}

// ---------------- 5. layer-1 sparse attention (block/row, warp/head) ---------
__global__ __launch_bounds__(256) void attn1() {
    int i = blockIdx.x;
    int tid = threadIdx.x;
    int head = tid >> 5, lane = tid & 31;
    __shared__ int   s_cols[MAXDEG];
    __shared__ float s_w[MAXDEG];
    __shared__ float s_p[HEADS][MAXDEG];
    int n = g_cnt[i];
    float di = g_dinv[i];
    for (int k = tid; k < n; k += 256) {
        int j = g_cols[i * MAXDEG + k];
        s_cols[k] = j;
        s_w[k]    = di * g_wv[i * MAXDEG + k] * g_dinv[j];   // dinv folded here
    }
    __syncthreads();

    float si = g_srcT[i * HEADS + head];
    float m = -1e30f;
    for (int k = lane; k < n; k += 32) {
        float e = lrelu(si + __ldg(g_dstT + s_cols[k] * HEADS + head));
        s_p[head][k] = e;
        m = fmaxf(m, e);
    }
#pragma unroll
    for (int o = 16; o; o >>= 1) m = fmaxf(m, __shfl_xor_sync(0xffffffffu, m, o));
    float s = 0.f;
    for (int k = lane; k < n; k += 32) {
        float p = __expf(s_p[head][k] - m);
        s_p[head][k] = p;
        s += p;
    }
#pragma unroll
    for (int o = 16; o; o >>= 1) s += __shfl_xor_sync(0xffffffffu, s, o);
    float inv = 1.f / s;
    __syncwarp();

    const __half2* Hh2 = (const __half2*)g_Hh;
    float2 acc = make_float2(0.f, 0.f);
#pragma unroll 4
    for (int k = 0; k < n; k++) {
        int j = s_cols[k];
        float coef = s_p[head][k] * inv * s_w[k];
        float2 v = __half22float2(__ldg(Hh2 + (size_t)j * (CAT / 2) + head * 32 + lane));
        acc.x = fmaf(coef, v.x, acc.x);
        acc.y = fmaf(coef, v.y, acc.y);
    }
    float2 o = make_float2(elu1(acc.x), elu1(acc.y));
    ((float2*)g_X1)[(size_t)i * (CAT / 2) + head * 32 + lane] = o;
}

// ---------------- 6. H2 = X1 @ W_out, src2/dst2 ------------------------------
__global__ void h2_srcdst(const float* __restrict__ W_out,
                          const float* __restrict__ a_out) {
    int i = blockIdx.x, tid = threadIdx.x;
    __shared__ float sx[CAT];
    __shared__ float sp[16][17];
    __shared__ float sh[NCLASS];
    sx[tid]       = g_X1[(size_t)i * CAT + tid];
    sx[tid + 256] = g_X1[(size_t)i * CAT + tid + 256];
    __syncthreads();
    int c = tid & 15, chunk = tid >> 4;
    float p = 0.f;
    int k0 = chunk * 32;
#pragma unroll 8
    for (int k = k0; k < k0 + 32; k++) p = fmaf(sx[k], __ldg(W_out + k * NCLASS + c), p);
    sp[chunk][c] = p;
    __syncthreads();
    if (tid < NCLASS) {
        float v = 0.f;
#pragma unroll
        for (int q = 0; q < 16; q++) v += sp[q][tid];
        g_H2[i * NCLASS + tid] = v;
        sh[tid] = v;
    }
    __syncthreads();
    if (tid == 0) {
        float s = 0.f, d = 0.f;
#pragma unroll
        for (int cc = 0; cc < NCLASS; cc++) {
            s = fmaf(sh[cc], __ldg(a_out + cc), s);
            d = fmaf(sh[cc], __ldg(a_out + NCLASS + cc), d);
        }
        g_s2[i] = s;
        g_d2[i] = d;
    }
}

// ---------------- 7. layer-2 sparse attention (warp per row) -----------------
__global__ void attn2() {
    int w = threadIdx.x >> 5, lane = threadIdx.x & 31;
    int i = blockIdx.x * 4 + w;
    __shared__ int   s_c[4][MAXDEG];
    __shared__ float s_w[4][MAXDEG];
    __shared__ float s_p[4][MAXDEG];
    if (i >= N_NODES) return;
    int n = g_cnt[i];
    float si = g_s2[i];
    float di = g_dinv[i];
    float m = -1e30f;
    for (int k = lane; k < n; k += 32) {
        int j = g_cols[i * MAXDEG + k];
        s_c[w][k] = j;
        s_w[w][k] = di * g_wv[i * MAXDEG + k] * g_dinv[j];
        float e = lrelu(si + g_d2[j]);
        s_p[w][k] = e;
        m = fmaxf(m, e);
    }
#pragma unroll
    for (int o = 16; o; o >>= 1) m = fmaxf(m, __shfl_xor_sync(0xffffffffu, m, o));
    float s = 0.f;
    for (int k = lane; k < n; k += 32) {
        float p = __expf(s_p[w][k] - m);
        s_p[w][k] = p;
        s += p;
    }
#pragma unroll
    for (int o = 16; o; o >>= 1) s += __shfl_xor_sync(0xffffffffu, s, o);
    float inv = 1.f / s;
    __syncwarp();
    if (lane < NCLASS) {
        float acc = 0.f;
        for (int k = 0; k < n; k++) {
            float coef = s_p[w][k] * inv * s_w[w][k];
            acc = fmaf(coef, g_H2[s_c[w][k] * NCLASS + lane], acc);
        }
        g_Z[i * NCLASS + lane] = elu1(elu1(acc));
    }
}

// ---------------- 8. FC head + log_softmax (warp per row) --------------------
__global__ void head_k(const float* __restrict__ FC1,
                       const float* __restrict__ FC2,
                       float* __restrict__ out) {
    int w = threadIdx.x >> 5, lane = threadIdx.x & 31;
    int row = blockIdx.x * 8 + w;
    if (row >= N_NODES) return;
    float z = (lane < NCLASS) ? g_Z[row * NCLASS + lane] : 0.f;
    float y1 = 0.f;
#pragma unroll
    for (int k = 0; k < NCLASS; k++) {
        float zk = __shfl_sync(0xffffffffu, z, k);
        if (lane < NCLASS) y1 = fmaf(zk, __ldg(FC1 + lane * NCLASS + k), y1);
    }
    y1 = elu1(y1);
    float y2 = 0.f;
#pragma unroll
    for (int k = 0; k < NCLASS; k++) {
        float yk = __shfl_sync(0xffffffffu, y1, k);
        if (lane < NCLASS) y2 = fmaf(yk, __ldg(FC2 + lane * NCLASS + k), y2);
    }
    y2 = elu1(y2);
    float v = (lane < NCLASS) ? y2 : -1e30f;
#pragma unroll
    for (int o = 8; o; o >>= 1) v = fmaxf(v, __shfl_xor_sync(0xffffffffu, v, o));
    float e = (lane < NCLASS) ? expf(y2 - v) : 0.f;
    float sum = e;
#pragma unroll
    for (int o = 8; o; o >>= 1) sum += __shfl_xor_sync(0xffffffffu, sum, o);
    if (lane < NCLASS) out[row * NCLASS + lane] = y2 - v - logf(sum);
}

// ---------------- launcher ---------------------------------------------------
extern "C" void kernel_launch(void* const* d_in, const int* in_sizes, int n_in,
                              void* d_out, int out_size) {
    const float* adj     = (const float*)d_in[0];
    const float* feat    = (const float*)d_in[1];
    const float* W_heads = (const float*)d_in[2];
    const float* a_heads = (const float*)d_in[3];
    const float* W_out   = (const float*)d_in[4];
    const float* a_out   = (const float*)d_in[5];
    const float* FC1     = (const float*)d_in[6];
    const float* FC2     = (const float*)d_in[7];
    float* out = (float*)d_out;

    pack_w     <<<IN_DIM, CAT>>>(W_heads);
    build_edges<<<N_NODES, 128>>>(adj);
    sgemm_H    <<<dim3(CAT / BN, (N_NODES + BM - 1) / BM), 256>>>(feat);
    srcdst1    <<<N_NODES, 256>>>(a_heads);
    attn1      <<<N_NODES, 256>>>();
    h2_srcdst  <<<N_NODES, 256>>>(W_out, a_out);
    attn2      <<<(N_NODES + 3) / 4, 128>>>();
    head_k     <<<(N_NODES + 7) / 8, 256>>>(FC1, FC2, out);
}

// round 6
// speedup vs baseline: 1.2609x; 1.2609x over previous
#include <cuda_runtime.h>
#include <cuda_fp16.h>
#include <math.h>
#include <stdint.h>

#define N_NODES 3000
#define IN_DIM  512
#define HID     64
#define HEADS   8
#define CAT     512
#define NCLASS  16
#define MAXDEG  256
#define ALPHA   0.2f

// ---------------- scratch -----------------------------------------------------
__device__ float  g_dinv[N_NODES];
__device__ int    g_cnt [N_NODES];
__device__ int    g_cols[N_NODES * MAXDEG];
__device__ float  g_wv  [N_NODES * MAXDEG];     // raw a1 (adj+I) values
__device__ float  g_Wc  [IN_DIM * CAT];         // packed W_heads -> [k][head*64+f]
__device__ __half g_Hh  [N_NODES * CAT];        // fp16 h for attn1 gather
__device__ float  g_srcT[N_NODES * HEADS];      // [node][head]
__device__ float  g_dstT[N_NODES * HEADS];
__device__ float  g_X1  [N_NODES * CAT];
__device__ float  g_H2  [N_NODES * NCLASS];
__device__ float  g_s2  [N_NODES];
__device__ float  g_d2  [N_NODES];
__device__ float  g_Z   [N_NODES * NCLASS];

__device__ __forceinline__ float elu1(float x) { return x > 0.f ? x : expm1f(x); }
__device__ __forceinline__ float lrelu(float x){ return x >= 0.f ? x : ALPHA * x; }
__device__ __forceinline__ uint32_t f2tf32(float f) {
    uint32_t u; asm("cvt.rna.tf32.f32 %0, %1;" : "=r"(u) : "f"(f)); return u;
}
__device__ __forceinline__ void mma_tf32(float* c, const uint32_t* a, const uint32_t* b) {
    asm volatile(
        "mma.sync.aligned.m16n8k8.row.col.f32.tf32.tf32.f32 "
        "{%0,%1,%2,%3}, {%4,%5,%6,%7}, {%8,%9}, {%0,%1,%2,%3};\n"
        : "+f"(c[0]), "+f"(c[1]), "+f"(c[2]), "+f"(c[3])
        : "r"(a[0]), "r"(a[1]), "r"(a[2]), "r"(a[3]), "r"(b[0]), "r"(b[1]));
}

// ---------------- 1. pack W_heads (split in 2 launches) -----------------------
__global__ void pack_w(const float* __restrict__ W_heads, int koff) {
    int k = blockIdx.x + koff;
    int c = threadIdx.x;
    g_Wc[k * CAT + c] = W_heads[(c >> 6) * (IN_DIM * HID) + k * HID + (c & 63)];
}

// ---------------- 2. edge build: 4 warps/row, column-segment partition --------
#define SEGQ 188
__global__ __launch_bounds__(128) void build_edges(const float* __restrict__ adj) {
    int row  = blockIdx.x;
    int tid  = threadIdx.x;
    int w    = tid >> 5, lane = tid & 31;
    __shared__ int   s_bufc[4][128];
    __shared__ float s_bufv[4][128];
    __shared__ int   s_cnt[4];
    __shared__ float s_sum[4];

    const float4* arow4 = (const float4*)(adj + (size_t)row * N_NODES);
    const int NQ = N_NODES / 4;
    int q0 = w * SEGQ;
    int q1 = min(q0 + SEGQ, NQ);

    int cnt = 0;
    float rsum = 0.f;
    for (int base = q0; base < q1; base += 32) {
        int q = base + lane;
        bool valid = q < q1;
        float a[4] = {0.f, 0.f, 0.f, 0.f};
        int j0 = q * 4;
        if (valid) {
            float4 v = arow4[q];
            a[0] = v.x; a[1] = v.y; a[2] = v.z; a[3] = v.w;
            if (row >= j0 && row < j0 + 4) a[row - j0] += 1.f;   // +I
        }
        rsum += a[0] + a[1] + a[2] + a[3];
#pragma unroll
        for (int t = 0; t < 4; t++) {
            bool has = valid && (a[t] > 0.f);
            unsigned msk = __ballot_sync(0xffffffffu, has);
            if (has) {
                int pos = cnt + __popc(msk & ((1u << lane) - 1u));
                if (pos < 128) {
                    s_bufc[w][pos] = j0 + t;
                    s_bufv[w][pos] = a[t];
                }
            }
            cnt += __popc(msk);
        }
    }
#pragma unroll
    for (int o = 16; o; o >>= 1) rsum += __shfl_xor_sync(0xffffffffu, rsum, o);
    if (lane == 0) { s_cnt[w] = cnt; s_sum[w] = rsum; }
    __syncthreads();

    int c0 = 0;
#pragma unroll
    for (int t = 0; t < 4; t++) if (t < w) c0 += s_cnt[t];
    int myc = min(s_cnt[w], 128);
    for (int k = lane; k < myc; k += 32) {
        int pos = c0 + k;
        if (pos < MAXDEG) {
            g_cols[row * MAXDEG + pos] = s_bufc[w][k];
            g_wv [row * MAXDEG + pos] = s_bufv[w][k];
        }
    }
    if (tid == 0) {
        int tot = s_cnt[0] + s_cnt[1] + s_cnt[2] + s_cnt[3];
        g_cnt[row]  = tot < MAXDEG ? tot : MAXDEG;
        g_dinv[row] = rsqrtf(s_sum[0] + s_sum[1] + s_sum[2] + s_sum[3]);
    }
}

// ---------------- 3. tf32 tensor-core GEMM + fused src/dst epilogue ----------
// H = X @ Wc, 64x64 block tile, BK=32, 4 warps (2x2), each 32x32.
// blockIdx.x = head (BN=64 = one head). Epilogue: g_Hh (fp16) + src/dst.
#define LDA 36
#define LDB 72
__global__ __launch_bounds__(128) void sgemm_tc(const float* __restrict__ A,
                                                const float* __restrict__ a_heads) {
    __shared__ uint32_t As[2][64 * LDA];
    __shared__ uint32_t Bs[2][32 * LDB];
    __shared__ float s_src[64][2];
    __shared__ float s_dst[64][2];

    int tid = threadIdx.x;
    int warp = tid >> 5, lane = tid & 31;
    int warp_m = warp & 1, warp_n = warp >> 1;
    int gid = lane >> 2, tig = lane & 3;
    int head = blockIdx.x;
    int brow = blockIdx.y * 64;
    int bcol = head * 64;

    // staging assignments
    int am = tid >> 1, akg = (tid & 1) * 16;          // A: row, k-group
    int bk = tid >> 2, bng = (tid & 3) * 16;          // B: k-row, n-group
    const float* Ag = A + (size_t)(brow + am) * IN_DIM + akg;
    bool aok = (brow + am) < N_NODES;
    const float* Bg = g_Wc + (size_t)bk * CAT + bcol + bng;
    const float4 z4 = make_float4(0.f, 0.f, 0.f, 0.f);

    float4 va[4], vb[4];
#pragma unroll
    for (int q = 0; q < 4; q++) {
        va[q] = aok ? *(const float4*)(Ag + q * 4) : z4;
        vb[q] = *(const float4*)(Bg + q * 4);
    }
    {
        uint32_t* ap = &As[0][am * LDA + akg];
        uint32_t* bp = &Bs[0][bk * LDB + bng];
#pragma unroll
        for (int q = 0; q < 4; q++) {
            uint4 ua = make_uint4(f2tf32(va[q].x), f2tf32(va[q].y), f2tf32(va[q].z), f2tf32(va[q].w));
            uint4 ub = make_uint4(f2tf32(vb[q].x), f2tf32(vb[q].y), f2tf32(vb[q].z), f2tf32(vb[q].w));
            *(uint4*)(ap + q * 4) = ua;
            *(uint4*)(bp + q * 4) = ub;
        }
    }
    __syncthreads();

    float c[2][4][4] = {};
    int cur = 0;
    const int NCHUNK = IN_DIM / 32;   // 16
    for (int ch = 0; ch < NCHUNK; ch++) {
        bool last = (ch == NCHUNK - 1);
        if (!last) {
            int k0 = (ch + 1) * 32;
#pragma unroll
            for (int q = 0; q < 4; q++) {
                va[q] = aok ? *(const float4*)(Ag + k0 + q * 4) : z4;
                vb[q] = *(const float4*)(Bg + (size_t)k0 * CAT + q * 4);
            }
        }
#pragma unroll
        for (int ks = 0; ks < 4; ks++) {
            int kk = ks * 8;
            uint32_t af[2][4], bf[4][2];
#pragma unroll
            for (int mt = 0; mt < 2; mt++) {
                const uint32_t* ap = &As[cur][(warp_m * 32 + mt * 16 + gid) * LDA + kk + tig];
                af[mt][0] = ap[0];
                af[mt][1] = ap[8 * LDA];
                af[mt][2] = ap[4];
                af[mt][3] = ap[8 * LDA + 4];
            }
#pragma unroll
            for (int nt = 0; nt < 4; nt++) {
                const uint32_t* bp = &Bs[cur][(kk + tig) * LDB + warp_n * 32 + nt * 8 + gid];
                bf[nt][0] = bp[0];
                bf[nt][1] = bp[4 * LDB];
            }
#pragma unroll
            for (int mt = 0; mt < 2; mt++)
#pragma unroll
                for (int nt = 0; nt < 4; nt++)
                    mma_tf32(c[mt][nt], af[mt], bf[nt]);
        }
        if (!last) {
            int nxt = cur ^ 1;
            uint32_t* ap = &As[nxt][am * LDA + akg];
            uint32_t* bp = &Bs[nxt][bk * LDB + bng];
#pragma unroll
            for (int q = 0; q < 4; q++) {
                uint4 ua = make_uint4(f2tf32(va[q].x), f2tf32(va[q].y), f2tf32(va[q].z), f2tf32(va[q].w));
                uint4 ub = make_uint4(f2tf32(vb[q].x), f2tf32(vb[q].y), f2tf32(vb[q].z), f2tf32(vb[q].w));
                *(uint4*)(ap + q * 4) = ua;
                *(uint4*)(bp + q * 4) = ub;
            }
        }
        __syncthreads();
        cur ^= 1;
    }

    // ---- epilogue: fp16 H store + fused src/dst reduction ----
    const float* av = a_heads + head * (2 * HID);
    float ps[2][2] = {}, pd[2][2] = {};
#pragma unroll
    for (int mt = 0; mt < 2; mt++) {
        int row0 = brow + warp_m * 32 + mt * 16 + gid;
#pragma unroll
        for (int nt = 0; nt < 4; nt++) {
            int cl = warp_n * 32 + nt * 8 + 2 * tig;       // local col in head
            float c0 = c[mt][nt][0], c1 = c[mt][nt][1];
            float c2 = c[mt][nt][2], c3 = c[mt][nt][3];
            float as0 = av[cl], as1 = av[cl + 1];
            float ad0 = av[64 + cl], ad1 = av[64 + cl + 1];
            ps[mt][0] += c0 * as0 + c1 * as1;
            pd[mt][0] += c0 * ad0 + c1 * ad1;
            ps[mt][1] += c2 * as0 + c3 * as1;
            pd[mt][1] += c2 * ad0 + c3 * ad1;
            int colg = bcol + cl;
            if (row0 < N_NODES)
                *(__half2*)(g_Hh + (size_t)row0 * CAT + colg) = __floats2half2_rn(c0, c1);
            if (row0 + 8 < N_NODES)
                *(__half2*)(g_Hh + (size_t)(row0 + 8) * CAT + colg) = __floats2half2_rn(c2, c3);
        }
    }
#pragma unroll
    for (int mt = 0; mt < 2; mt++)
#pragma unroll
        for (int h = 0; h < 2; h++) {
            ps[mt][h] += __shfl_xor_sync(0xffffffffu, ps[mt][h], 1);
            ps[mt][h] += __shfl_xor_sync(0xffffffffu, ps[mt][h], 2);
            pd[mt][h] += __shfl_xor_sync(0xffffffffu, pd[mt][h], 1);
            pd[mt][h] += __shfl_xor_sync(0xffffffffu, pd[mt][h], 2);
        }
    if (tig == 0) {
#pragma unroll
        for (int mt = 0; mt < 2; mt++)
#pragma unroll
            for (int h = 0; h < 2; h++) {
                int rl = warp_m * 32 + mt * 16 + gid + 8 * h;
                s_src[rl][warp_n] = ps[mt][h];
                s_dst[rl][warp_n] = pd[mt][h];
            }
    }
    __syncthreads();
    if (tid < 128) {
        int rl = tid >> 1, which = tid & 1;
        int row = brow + rl;
        if (row < N_NODES) {
            if (which == 0) g_srcT[row * HEADS + head] = s_src[rl][0] + s_src[rl][1];
            else            g_dstT[row * HEADS + head] = s_dst[rl][0] + s_dst[rl][1];
        }
    }
}

// ---------------- 4. layer-1 sparse attention (block/row, warp/head) ---------
__global__ __launch_bounds__(256) void attn1() {
    int i = blockIdx.x;
    int tid = threadIdx.x;
    int head = tid >> 5, lane = tid & 31;
    __shared__ int   s_cols[MAXDEG];
    __shared__ float s_w[MAXDEG];
    __shared__ float s_p[HEADS][MAXDEG];
    int n = g_cnt[i];
    float di = g_dinv[i];
    for (int k = tid; k < n; k += 256) {
        int j = g_cols[i * MAXDEG + k];
        s_cols[k] = j;
        s_w[k]    = di * g_wv[i * MAXDEG + k] * g_dinv[j];
    }
    __syncthreads();

    float si = g_srcT[i * HEADS + head];
    float m = -1e30f;
    for (int k = lane; k < n; k += 32) {
        float e = lrelu(si + __ldg(g_dstT + s_cols[k] * HEADS + head));
        s_p[head][k] = e;
        m = fmaxf(m, e);
    }
#pragma unroll
    for (int o = 16; o; o >>= 1) m = fmaxf(m, __shfl_xor_sync(0xffffffffu, m, o));
    float s = 0.f;
    for (int k = lane; k < n; k += 32) {
        float p = __expf(s_p[head][k] - m);
        s_p[head][k] = p;
        s += p;
    }
#pragma unroll
    for (int o = 16; o; o >>= 1) s += __shfl_xor_sync(0xffffffffu, s, o);
    float inv = 1.f / s;
    __syncwarp();

    const __half2* Hh2 = (const __half2*)g_Hh;
    float2 acc = make_float2(0.f, 0.f);
#pragma unroll 4
    for (int k = 0; k < n; k++) {
        int j = s_cols[k];
        float coef = s_p[head][k] * inv * s_w[k];
        float2 v = __half22float2(__ldg(Hh2 + (size_t)j * (CAT / 2) + head * 32 + lane));
        acc.x = fmaf(coef, v.x, acc.x);
        acc.y = fmaf(coef, v.y, acc.y);
    }
    float2 o = make_float2(elu1(acc.x), elu1(acc.y));
    ((float2*)g_X1)[(size_t)i * (CAT / 2) + head * 32 + lane] = o;
}

// ---------------- 5. H2 = X1 @ W_out, src2/dst2 ------------------------------
__global__ void h2_srcdst(const float* __restrict__ W_out,
                          const float* __restrict__ a_out) {
    int i = blockIdx.x, tid = threadIdx.x;
    __shared__ float sx[CAT];
    __shared__ float sp[16][17];
    __shared__ float sh[NCLASS];
    sx[tid]       = g_X1[(size_t)i * CAT + tid];
    sx[tid + 256] = g_X1[(size_t)i * CAT + tid + 256];
    __syncthreads();
    int c = tid & 15, chunk = tid >> 4;
    float p = 0.f;
    int k0 = chunk * 32;
#pragma unroll 8
    for (int k = k0; k < k0 + 32; k++) p = fmaf(sx[k], __ldg(W_out + k * NCLASS + c), p);
    sp[chunk][c] = p;
    __syncthreads();
    if (tid < NCLASS) {
        float v = 0.f;
#pragma unroll
        for (int q = 0; q < 16; q++) v += sp[q][tid];
        g_H2[i * NCLASS + tid] = v;
        sh[tid] = v;
    }
    __syncthreads();
    if (tid == 0) {
        float s = 0.f, d = 0.f;
#pragma unroll
        for (int cc = 0; cc < NCLASS; cc++) {
            s = fmaf(sh[cc], __ldg(a_out + cc), s);
            d = fmaf(sh[cc], __ldg(a_out + NCLASS + cc), d);
        }
        g_s2[i] = s;
        g_d2[i] = d;
    }
}

// ---------------- 6. layer-2 sparse attention (warp per row) -----------------
__global__ void attn2() {
    int w = threadIdx.x >> 5, lane = threadIdx.x & 31;
    int i = blockIdx.x * 4 + w;
    __shared__ int   s_c[4][MAXDEG];
    __shared__ float s_w[4][MAXDEG];
    __shared__ float s_p[4][MAXDEG];
    if (i >= N_NODES) return;
    int n = g_cnt[i];
    float si = g_s2[i];
    float di = g_dinv[i];
    float m = -1e30f;
    for (int k = lane; k < n; k += 32) {
        int j = g_cols[i * MAXDEG + k];
        s_c[w][k] = j;
        s_w[w][k] = di * g_wv[i * MAXDEG + k] * g_dinv[j];
        float e = lrelu(si + g_d2[j]);
        s_p[w][k] = e;
        m = fmaxf(m, e);
    }
#pragma unroll
    for (int o = 16; o; o >>= 1) m = fmaxf(m, __shfl_xor_sync(0xffffffffu, m, o));
    float s = 0.f;
    for (int k = lane; k < n; k += 32) {
        float p = __expf(s_p[w][k] - m);
        s_p[w][k] = p;
        s += p;
    }
#pragma unroll
    for (int o = 16; o; o >>= 1) s += __shfl_xor_sync(0xffffffffu, s, o);
    float inv = 1.f / s;
    __syncwarp();
    if (lane < NCLASS) {
        float acc = 0.f;
        for (int k = 0; k < n; k++) {
            float coef = s_p[w][k] * inv * s_w[w][k];
            acc = fmaf(coef, g_H2[s_c[w][k] * NCLASS + lane], acc);
        }
        g_Z[i * NCLASS + lane] = elu1(elu1(acc));
    }
}

// ---------------- 7. FC head + log_softmax (warp per row) --------------------
__global__ void head_k(const float* __restrict__ FC1,
                       const float* __restrict__ FC2,
                       float* __restrict__ out) {
    int w = threadIdx.x >> 5, lane = threadIdx.x & 31;
    int row = blockIdx.x * 8 + w;
    if (row >= N_NODES) return;
    float z = (lane < NCLASS) ? g_Z[row * NCLASS + lane] : 0.f;
    float y1 = 0.f;
#pragma unroll
    for (int k = 0; k < NCLASS; k++) {
        float zk = __shfl_sync(0xffffffffu, z, k);
        if (lane < NCLASS) y1 = fmaf(zk, __ldg(FC1 + lane * NCLASS + k), y1);
    }
    y1 = elu1(y1);
    float y2 = 0.f;
#pragma unroll
    for (int k = 0; k < NCLASS; k++) {
        float yk = __shfl_sync(0xffffffffu, y1, k);
        if (lane < NCLASS) y2 = fmaf(yk, __ldg(FC2 + lane * NCLASS + k), y2);
    }
    y2 = elu1(y2);
    float v = (lane < NCLASS) ? y2 : -1e30f;
#pragma unroll
    for (int o = 8; o; o >>= 1) v = fmaxf(v, __shfl_xor_sync(0xffffffffu, v, o));
    float e = (lane < NCLASS) ? expf(y2 - v) : 0.f;
    float sum = e;
#pragma unroll
    for (int o = 8; o; o >>= 1) sum += __shfl_xor_sync(0xffffffffu, sum, o);
    if (lane < NCLASS) out[row * NCLASS + lane] = y2 - v - logf(sum);
}

// ---------------- launcher ---------------------------------------------------
extern "C" void kernel_launch(void* const* d_in, const int* in_sizes, int n_in,
                              void* d_out, int out_size) {
    const float* adj     = (const float*)d_in[0];
    const float* feat    = (const float*)d_in[1];
    const float* W_heads = (const float*)d_in[2];
    const float* a_heads = (const float*)d_in[3];
    const float* W_out   = (const float*)d_in[4];
    const float* a_out   = (const float*)d_in[5];
    const float* FC1     = (const float*)d_in[6];
    const float* FC2     = (const float*)d_in[7];
    float* out = (float*)d_out;

    pack_w     <<<IN_DIM / 2, CAT>>>(W_heads, 0);
    pack_w     <<<IN_DIM / 2, CAT>>>(W_heads, IN_DIM / 2);
    build_edges<<<N_NODES, 128>>>(adj);
    sgemm_tc   <<<dim3(HEADS, (N_NODES + 63) / 64), 128>>>(feat, a_heads);  // launch #4: profiled
    attn1      <<<N_NODES, 256>>>();
    h2_srcdst  <<<N_NODES, 256>>>(W_out, a_out);
    attn2      <<<(N_NODES + 3) / 4, 128>>>();
    head_k     <<<(N_NODES + 7) / 8, 256>>>(FC1, FC2, out);
}

// round 7
// speedup vs baseline: 1.4209x; 1.1269x over previous
#include <cuda_runtime.h>
#include <cuda_fp16.h>
#include <math.h>
#include <stdint.h>

#define N_NODES 3000
#define NROW_P  3008      // padded rows for g_At
#define IN_DIM  512
#define HID     64
#define HEADS   8
#define CAT     512
#define NCLASS  16
#define MAXDEG  256
#define ALPHA   0.2f
#define NCHUNK  16        // IN_DIM/32

// ---------------- scratch -----------------------------------------------------
__device__ float    g_dinv[N_NODES];
__device__ int      g_cnt [N_NODES];
__device__ int      g_cols[N_NODES * MAXDEG];
__device__ float    g_wv  [N_NODES * MAXDEG];
__device__ uint32_t g_At  [NCHUNK * NROW_P * 32];       // tf32 A, k-interleaved
__device__ uint32_t g_WcT [HEADS * NCHUNK * 64 * 32];   // tf32 W, transposed+interleaved
__device__ __half   g_Hh  [N_NODES * CAT];
__device__ float    g_srcT[N_NODES * HEADS];
__device__ float    g_dstT[N_NODES * HEADS];
__device__ float    g_X1  [N_NODES * CAT];
__device__ float    g_H2  [N_NODES * NCLASS];
__device__ float    g_s2  [N_NODES];
__device__ float    g_d2  [N_NODES];
__device__ float    g_Z   [N_NODES * NCLASS];

__device__ __forceinline__ float elu1(float x) { return x > 0.f ? x : expm1f(x); }
__device__ __forceinline__ float lrelu(float x){ return x >= 0.f ? x : ALPHA * x; }
__device__ __forceinline__ uint32_t f2tf32(float f) {
    uint32_t u; asm("cvt.rna.tf32.f32 %0, %1;" : "=r"(u) : "f"(f)); return u;
}
__device__ __forceinline__ void mma_tf32(float* c, const uint32_t* a, const uint32_t* b) {
    asm volatile(
        "mma.sync.aligned.m16n8k8.row.col.f32.tf32.tf32.f32 "
        "{%0,%1,%2,%3}, {%4,%5,%6,%7}, {%8,%9}, {%0,%1,%2,%3};\n"
        : "+f"(c[0]), "+f"(c[1]), "+f"(c[2]), "+f"(c[3])
        : "r"(a[0]), "r"(a[1]), "r"(a[2]), "r"(a[3]), "r"(b[0]), "r"(b[1]));
}

// ---------------- 1. pack W_heads -> g_WcT (tf32, interleaved-transposed) ----
// layout: g_WcT[((h*16+ch)*64 + n)*32 + c], c = (kl&3)*8 + (kl>>2)
__global__ void pack_w(const float* __restrict__ W_heads) {
    int h = blockIdx.x, ch = blockIdx.y;
    int t = threadIdx.x;                       // 256
#pragma unroll
    for (int i = 0; i < 8; i++) {
        int idx = t * 8 + i;                   // 0..2047
        int n = idx >> 5, c = idx & 31;
        int kl = (c & 7) * 4 + (c >> 3);
        float v = W_heads[((size_t)h * IN_DIM + ch * 32 + kl) * HID + n];
        g_WcT[(((size_t)h * NCHUNK + ch) * 64 + n) * 32 + c] = f2tf32(v);
    }
}

// ---------------- 2. prep A: feat -> g_At (tf32, k-interleaved) --------------
__global__ void prep_A(const float* __restrict__ feat) {
    int row = blockIdx.x;
    int t = threadIdx.x;                       // 128
    int k = t * 4;
    int ch = k >> 5, kl = k & 31, m = kl >> 2;
    float4 v = *(const float4*)(feat + (size_t)row * IN_DIM + k);
    uint32_t* dst = g_At + ((size_t)ch * NROW_P + row) * 32;
    dst[0 * 8 + m] = f2tf32(v.x);
    dst[1 * 8 + m] = f2tf32(v.y);
    dst[2 * 8 + m] = f2tf32(v.z);
    dst[3 * 8 + m] = f2tf32(v.w);
}

// ---------------- 3. tf32 GEMM + fused src/dst epilogue ----------------------
#define LDI 36
__global__ __launch_bounds__(128) void sgemm_tc(const float* __restrict__ a_heads) {
    __shared__ uint32_t As[2][64 * LDI];
    __shared__ uint32_t Bs[2][64 * LDI];
    __shared__ float s_src[64][2];
    __shared__ float s_dst[64][2];

    int tid = threadIdx.x;
    int warp = tid >> 5, lane = tid & 31;
    int warp_m = warp & 1, warp_n = warp >> 1;
    int gid = lane >> 2, tig = lane & 3;
    int head = blockIdx.x;
    int brow = blockIdx.y * 64;
    int bcol = head * 64;

    // staging mapping: thread t copies 4 uint4; idx = t*4 + i*512
    int srow = tid >> 3, scol = (tid & 7) * 4;
    const uint32_t* Asrc = g_At + (size_t)brow * 32;                 // + ch*NROW_P*32
    const uint32_t* Bsrc = g_WcT + (size_t)head * NCHUNK * 64 * 32;  // + ch*2048

    uint4 va[4], vb[4];
#pragma unroll
    for (int i = 0; i < 4; i++) {
        va[i] = *(const uint4*)(Asrc + (size_t)tid * 4 + i * 512);
        vb[i] = *(const uint4*)(Bsrc + (size_t)tid * 4 + i * 512);
    }
#pragma unroll
    for (int i = 0; i < 4; i++) {
        *(uint4*)&As[0][(srow + i * 16) * LDI + scol] = va[i];
        *(uint4*)&Bs[0][(srow + i * 16) * LDI + scol] = vb[i];
    }
    __syncthreads();

    float c[2][4][4] = {};
    int cur = 0;
    for (int ch = 0; ch < NCHUNK; ch++) {
        bool last = (ch == NCHUNK - 1);
        if (!last) {
            const uint32_t* An = Asrc + (size_t)(ch + 1) * NROW_P * 32;
            const uint32_t* Bn = Bsrc + (size_t)(ch + 1) * 2048;
#pragma unroll
            for (int i = 0; i < 4; i++) {
                va[i] = *(const uint4*)(An + (size_t)tid * 4 + i * 512);
                vb[i] = *(const uint4*)(Bn + (size_t)tid * 4 + i * 512);
            }
        }
        // fragment loads: all vectorized
        uint32_t alo[2][8], ahi[2][8], bf[4][8];
#pragma unroll
        for (int mt = 0; mt < 2; mt++) {
            int rowA = warp_m * 32 + mt * 16 + gid;
            *(uint4*)&alo[mt][0] = *(uint4*)&As[cur][rowA * LDI + tig * 8];
            *(uint4*)&alo[mt][4] = *(uint4*)&As[cur][rowA * LDI + tig * 8 + 4];
            *(uint4*)&ahi[mt][0] = *(uint4*)&As[cur][(rowA + 8) * LDI + tig * 8];
            *(uint4*)&ahi[mt][4] = *(uint4*)&As[cur][(rowA + 8) * LDI + tig * 8 + 4];
        }
#pragma unroll
        for (int nt = 0; nt < 4; nt++) {
            int rowB = warp_n * 32 + nt * 8 + gid;
            *(uint4*)&bf[nt][0] = *(uint4*)&Bs[cur][rowB * LDI + tig * 8];
            *(uint4*)&bf[nt][4] = *(uint4*)&Bs[cur][rowB * LDI + tig * 8 + 4];
        }
#pragma unroll
        for (int ks = 0; ks < 4; ks++) {
#pragma unroll
            for (int mt = 0; mt < 2; mt++) {
                uint32_t a[4] = {alo[mt][2 * ks], ahi[mt][2 * ks],
                                 alo[mt][2 * ks + 1], ahi[mt][2 * ks + 1]};
#pragma unroll
                for (int nt = 0; nt < 4; nt++) {
                    uint32_t b[2] = {bf[nt][2 * ks], bf[nt][2 * ks + 1]};
                    mma_tf32(c[mt][nt], a, b);
                }
            }
        }
        if (!last) {
            int nxt = cur ^ 1;
#pragma unroll
            for (int i = 0; i < 4; i++) {
                *(uint4*)&As[nxt][(srow + i * 16) * LDI + scol] = va[i];
                *(uint4*)&Bs[nxt][(srow + i * 16) * LDI + scol] = vb[i];
            }
        }
        __syncthreads();
        cur ^= 1;
    }

    // ---- epilogue: fp16 H store + fused src/dst reduction ----
    const float* av = a_heads + head * (2 * HID);
    float ps[2][2] = {}, pd[2][2] = {};
#pragma unroll
    for (int mt = 0; mt < 2; mt++) {
        int row0 = brow + warp_m * 32 + mt * 16 + gid;
#pragma unroll
        for (int nt = 0; nt < 4; nt++) {
            int cl = warp_n * 32 + nt * 8 + 2 * tig;
            float c0 = c[mt][nt][0], c1 = c[mt][nt][1];
            float c2 = c[mt][nt][2], c3 = c[mt][nt][3];
            float as0 = av[cl], as1 = av[cl + 1];
            float ad0 = av[64 + cl], ad1 = av[64 + cl + 1];
            ps[mt][0] += c0 * as0 + c1 * as1;
            pd[mt][0] += c0 * ad0 + c1 * ad1;
            ps[mt][1] += c2 * as0 + c3 * as1;
            pd[mt][1] += c2 * ad0 + c3 * ad1;
            int colg = bcol + cl;
            if (row0 < N_NODES)
                *(__half2*)(g_Hh + (size_t)row0 * CAT + colg) = __floats2half2_rn(c0, c1);
            if (row0 + 8 < N_NODES)
                *(__half2*)(g_Hh + (size_t)(row0 + 8) * CAT + colg) = __floats2half2_rn(c2, c3);
        }
    }
#pragma unroll
    for (int mt = 0; mt < 2; mt++)
#pragma unroll
        for (int h = 0; h < 2; h++) {
            ps[mt][h] += __shfl_xor_sync(0xffffffffu, ps[mt][h], 1);
            ps[mt][h] += __shfl_xor_sync(0xffffffffu, ps[mt][h], 2);
            pd[mt][h] += __shfl_xor_sync(0xffffffffu, pd[mt][h], 1);
            pd[mt][h] += __shfl_xor_sync(0xffffffffu, pd[mt][h], 2);
        }
    if (tig == 0) {
#pragma unroll
        for (int mt = 0; mt < 2; mt++)
#pragma unroll
            for (int h = 0; h < 2; h++) {
                int rl = warp_m * 32 + mt * 16 + gid + 8 * h;
                s_src[rl][warp_n] = ps[mt][h];
                s_dst[rl][warp_n] = pd[mt][h];
            }
    }
    __syncthreads();
    {
        int rl = tid >> 1, which = tid & 1;
        int row = brow + rl;
        if (row < N_NODES) {
            if (which == 0) g_srcT[row * HEADS + head] = s_src[rl][0] + s_src[rl][1];
            else            g_dstT[row * HEADS + head] = s_dst[rl][0] + s_dst[rl][1];
        }
    }
}

// ---------------- 4. edge build: 4 warps/row ---------------------------------
#define SEGQ 188
__global__ __launch_bounds__(128) void build_edges(const float* __restrict__ adj) {
    int row  = blockIdx.x;
    int tid  = threadIdx.x;
    int w    = tid >> 5, lane = tid & 31;
    __shared__ int   s_bufc[4][128];
    __shared__ float s_bufv[4][128];
    __shared__ int   s_cnt[4];
    __shared__ float s_sum[4];

    const float4* arow4 = (const float4*)(adj + (size_t)row * N_NODES);
    const int NQ = N_NODES / 4;
    int q0 = w * SEGQ;
    int q1 = min(q0 + SEGQ, NQ);

    int cnt = 0;
    float rsum = 0.f;
    for (int base = q0; base < q1; base += 32) {
        int q = base + lane;
        bool valid = q < q1;
        float a[4] = {0.f, 0.f, 0.f, 0.f};
        int j0 = q * 4;
        if (valid) {
            float4 v = arow4[q];
            a[0] = v.x; a[1] = v.y; a[2] = v.z; a[3] = v.w;
            if (row >= j0 && row < j0 + 4) a[row - j0] += 1.f;
        }
        rsum += a[0] + a[1] + a[2] + a[3];
#pragma unroll
        for (int t = 0; t < 4; t++) {
            bool has = valid && (a[t] > 0.f);
            unsigned msk = __ballot_sync(0xffffffffu, has);
            if (has) {
                int pos = cnt + __popc(msk & ((1u << lane) - 1u));
                if (pos < 128) {
                    s_bufc[w][pos] = j0 + t;
                    s_bufv[w][pos] = a[t];
                }
            }
            cnt += __popc(msk);
        }
    }
#pragma unroll
    for (int o = 16; o; o >>= 1) rsum += __shfl_xor_sync(0xffffffffu, rsum, o);
    if (lane == 0) { s_cnt[w] = cnt; s_sum[w] = rsum; }
    __syncthreads();

    int c0 = 0;
#pragma unroll
    for (int t = 0; t < 4; t++) if (t < w) c0 += s_cnt[t];
    int myc = min(s_cnt[w], 128);
    for (int k = lane; k < myc; k += 32) {
        int pos = c0 + k;
        if (pos < MAXDEG) {
            g_cols[row * MAXDEG + pos] = s_bufc[w][k];
            g_wv [row * MAXDEG + pos] = s_bufv[w][k];
        }
    }
    if (tid == 0) {
        int tot = s_cnt[0] + s_cnt[1] + s_cnt[2] + s_cnt[3];
        g_cnt[row]  = tot < MAXDEG ? tot : MAXDEG;
        g_dinv[row] = rsqrtf(s_sum[0] + s_sum[1] + s_sum[2] + s_sum[3]);
    }
}

// ---------------- 5. layer-1 sparse attention --------------------------------
__global__ __launch_bounds__(256) void attn1() {
    int i = blockIdx.x;
    int tid = threadIdx.x;
    int head = tid >> 5, lane = tid & 31;
    __shared__ int   s_cols[MAXDEG];
    __shared__ float s_w[MAXDEG];
    __shared__ float s_p[HEADS][MAXDEG];
    int n = g_cnt[i];
    float di = g_dinv[i];
    for (int k = tid; k < n; k += 256) {
        int j = g_cols[i * MAXDEG + k];
        s_cols[k] = j;
        s_w[k]    = di * g_wv[i * MAXDEG + k] * g_dinv[j];
    }
    __syncthreads();

    float si = g_srcT[i * HEADS + head];
    float m = -1e30f;
    for (int k = lane; k < n; k += 32) {
        float e = lrelu(si + __ldg(g_dstT + s_cols[k] * HEADS + head));
        s_p[head][k] = e;
        m = fmaxf(m, e);
    }
#pragma unroll
    for (int o = 16; o; o >>= 1) m = fmaxf(m, __shfl_xor_sync(0xffffffffu, m, o));
    float s = 0.f;
    for (int k = lane; k < n; k += 32) {
        float p = __expf(s_p[head][k] - m);
        s_p[head][k] = p;
        s += p;
    }
#pragma unroll
    for (int o = 16; o; o >>= 1) s += __shfl_xor_sync(0xffffffffu, s, o);
    float inv = 1.f / s;
    __syncwarp();

    const __half2* Hh2 = (const __half2*)g_Hh;
    float2 acc = make_float2(0.f, 0.f);
#pragma unroll 4
    for (int k = 0; k < n; k++) {
        int j = s_cols[k];
        float coef = s_p[head][k] * inv * s_w[k];
        float2 v = __half22float2(__ldg(Hh2 + (size_t)j * (CAT / 2) + head * 32 + lane));
        acc.x = fmaf(coef, v.x, acc.x);
        acc.y = fmaf(coef, v.y, acc.y);
    }
    float2 o = make_float2(elu1(acc.x), elu1(acc.y));
    ((float2*)g_X1)[(size_t)i * (CAT / 2) + head * 32 + lane] = o;
}

// ---------------- 6. H2 = X1 @ W_out, src2/dst2 ------------------------------
__global__ void h2_srcdst(const float* __restrict__ W_out,
                          const float* __restrict__ a_out) {
    int i = blockIdx.x, tid = threadIdx.x;
    __shared__ float sx[CAT];
    __shared__ float sp[16][17];
    __shared__ float sh[NCLASS];
    sx[tid]       = g_X1[(size_t)i * CAT + tid];
    sx[tid + 256] = g_X1[(size_t)i * CAT + tid + 256];
    __syncthreads();
    int c = tid & 15, chunk = tid >> 4;
    float p = 0.f;
    int k0 = chunk * 32;
#pragma unroll 8
    for (int k = k0; k < k0 + 32; k++) p = fmaf(sx[k], __ldg(W_out + k * NCLASS + c), p);
    sp[chunk][c] = p;
    __syncthreads();
    if (tid < NCLASS) {
        float v = 0.f;
#pragma unroll
        for (int q = 0; q < 16; q++) v += sp[q][tid];
        g_H2[i * NCLASS + tid] = v;
        sh[tid] = v;
    }
    __syncthreads();
    if (tid == 0) {
        float s = 0.f, d = 0.f;
#pragma unroll
        for (int cc = 0; cc < NCLASS; cc++) {
            s = fmaf(sh[cc], __ldg(a_out + cc), s);
            d = fmaf(sh[cc], __ldg(a_out + NCLASS + cc), d);
        }
        g_s2[i] = s;
        g_d2[i] = d;
    }
}

// ---------------- 7. layer-2 sparse attention --------------------------------
__global__ void attn2() {
    int w = threadIdx.x >> 5, lane = threadIdx.x & 31;
    int i = blockIdx.x * 4 + w;
    __shared__ int   s_c[4][MAXDEG];
    __shared__ float s_w[4][MAXDEG];
    __shared__ float s_p[4][MAXDEG];
    if (i >= N_NODES) return;
    int n = g_cnt[i];
    float si = g_s2[i];
    float di = g_dinv[i];
    float m = -1e30f;
    for (int k = lane; k < n; k += 32) {
        int j = g_cols[i * MAXDEG + k];
        s_c[w][k] = j;
        s_w[w][k] = di * g_wv[i * MAXDEG + k] * g_dinv[j];
        float e = lrelu(si + g_d2[j]);
        s_p[w][k] = e;
        m = fmaxf(m, e);
    }
#pragma unroll
    for (int o = 16; o; o >>= 1) m = fmaxf(m, __shfl_xor_sync(0xffffffffu, m, o));
    float s = 0.f;
    for (int k = lane; k < n; k += 32) {
        float p = __expf(s_p[w][k] - m);
        s_p[w][k] = p;
        s += p;
    }
#pragma unroll
    for (int o = 16; o; o >>= 1) s += __shfl_xor_sync(0xffffffffu, s, o);
    float inv = 1.f / s;
    __syncwarp();
    if (lane < NCLASS) {
        float acc = 0.f;
        for (int k = 0; k < n; k++) {
            float coef = s_p[w][k] * inv * s_w[w][k];
            acc = fmaf(coef, g_H2[s_c[w][k] * NCLASS + lane], acc);
        }
        g_Z[i * NCLASS + lane] = elu1(elu1(acc));
    }
}

// ---------------- 8. FC head + log_softmax -----------------------------------
__global__ void head_k(const float* __restrict__ FC1,
                       const float* __restrict__ FC2,
                       float* __restrict__ out) {
    int w = threadIdx.x >> 5, lane = threadIdx.x & 31;
    int row = blockIdx.x * 8 + w;
    if (row >= N_NODES) return;
    float z = (lane < NCLASS) ? g_Z[row * NCLASS + lane] : 0.f;
    float y1 = 0.f;
#pragma unroll
    for (int k = 0; k < NCLASS; k++) {
        float zk = __shfl_sync(0xffffffffu, z, k);
        if (lane < NCLASS) y1 = fmaf(zk, __ldg(FC1 + lane * NCLASS + k), y1);
    }
    y1 = elu1(y1);
    float y2 = 0.f;
#pragma unroll
    for (int k = 0; k < NCLASS; k++) {
        float yk = __shfl_sync(0xffffffffu, y1, k);
        if (lane < NCLASS) y2 = fmaf(yk, __ldg(FC2 + lane * NCLASS + k), y2);
    }
    y2 = elu1(y2);
    float v = (lane < NCLASS) ? y2 : -1e30f;
#pragma unroll
    for (int o = 8; o; o >>= 1) v = fmaxf(v, __shfl_xor_sync(0xffffffffu, v, o));
    float e = (lane < NCLASS) ? expf(y2 - v) : 0.f;
    float sum = e;
#pragma unroll
    for (int o = 8; o; o >>= 1) sum += __shfl_xor_sync(0xffffffffu, sum, o);
    if (lane < NCLASS) out[row * NCLASS + lane] = y2 - v - logf(sum);
}

// ---------------- launcher ---------------------------------------------------
extern "C" void kernel_launch(void* const* d_in, const int* in_sizes, int n_in,
                              void* d_out, int out_size) {
    const float* adj     = (const float*)d_in[0];
    const float* feat    = (const float*)d_in[1];
    const float* W_heads = (const float*)d_in[2];
    const float* a_heads = (const float*)d_in[3];
    const float* W_out   = (const float*)d_in[4];
    const float* a_out   = (const float*)d_in[5];
    const float* FC1     = (const float*)d_in[6];
    const float* FC2     = (const float*)d_in[7];
    float* out = (float*)d_out;

    pack_w     <<<dim3(HEADS, NCHUNK), 256>>>(W_heads);                  // 1
    prep_A     <<<N_NODES, 128>>>(feat);                                 // 2
    sgemm_tc   <<<dim3(HEADS, (N_NODES + 63) / 64), 128>>>(a_heads);     // 3
    build_edges<<<N_NODES, 128>>>(adj);                                  // 4 (profiled)
    attn1      <<<N_NODES, 256>>>();                                     // 5
    h2_srcdst  <<<N_NODES, 256>>>(W_out, a_out);                         // 6
    attn2      <<<(N_NODES + 3) / 4, 128>>>();                           // 7
    head_k     <<<(N_NODES + 7) / 8, 256>>>(FC1, FC2, out);              // 8
}

// round 8
// speedup vs baseline: 1.4846x; 1.0448x over previous
#include <cuda_runtime.h>
#include <cuda_fp16.h>
#include <math.h>
#include <stdint.h>

#define N_NODES 3000
#define NROW_P  3008
#define IN_DIM  512
#define HID     64
#define HEADS   8
#define CAT     512
#define NCLASS  16
#define MAXDEG  256
#define ALPHA   0.2f
#define NCHUNK  16        // IN_DIM/32

// ---------------- scratch -----------------------------------------------------
__device__ float    g_dinv[N_NODES];
__device__ float    g_dsc [N_NODES];                    // diagonal a1 value (1 or 2)
__device__ int      g_cnt [N_NODES];
__device__ int      g_cols[N_NODES * MAXDEG];
__device__ uint32_t g_At  [NCHUNK * NROW_P * 32];       // tf32 A, k-interleaved
__device__ uint32_t g_WcT [HEADS * NCHUNK * 64 * 32];   // tf32 W, transposed+interleaved
__device__ __half   g_Hh  [N_NODES * CAT];
__device__ float    g_srcT[N_NODES * HEADS];
__device__ float    g_dstT[N_NODES * HEADS];
__device__ float    g_X1  [N_NODES * CAT];
__device__ float    g_H2  [N_NODES * NCLASS];
__device__ float    g_s2  [N_NODES];
__device__ float    g_d2  [N_NODES];
__device__ float    g_Z   [N_NODES * NCLASS];

__device__ __forceinline__ float elu1(float x) { return x > 0.f ? x : expm1f(x); }
__device__ __forceinline__ float lrelu(float x){ return x >= 0.f ? x : ALPHA * x; }
__device__ __forceinline__ uint32_t f2tf32(float f) {
    uint32_t u; asm("cvt.rna.tf32.f32 %0, %1;" : "=r"(u) : "f"(f)); return u;
}
__device__ __forceinline__ void mma_tf32(float* c, const uint32_t* a, const uint32_t* b) {
    asm volatile(
        "mma.sync.aligned.m16n8k8.row.col.f32.tf32.tf32.f32 "
        "{%0,%1,%2,%3}, {%4,%5,%6,%7}, {%8,%9}, {%0,%1,%2,%3};\n"
        : "+f"(c[0]), "+f"(c[1]), "+f"(c[2]), "+f"(c[3])
        : "r"(a[0]), "r"(a[1]), "r"(a[2]), "r"(a[3]), "r"(b[0]), "r"(b[1]));
}

// ---------------- 1. fused prep: pack_w (blocks 0..127) + prep_A (rest) ------
__global__ __launch_bounds__(256) void prep_all(const float* __restrict__ W_heads,
                                                const float* __restrict__ feat) {
    int b = blockIdx.x;
    int t = threadIdx.x;
    if (b < HEADS * NCHUNK) {
        int h = b >> 4, ch = b & 15;
#pragma unroll
        for (int i = 0; i < 8; i++) {
            int idx = t * 8 + i;                   // 0..2047
            int n = idx >> 5, c = idx & 31;
            int kl = (c & 7) * 4 + (c >> 3);
            float v = W_heads[((size_t)h * IN_DIM + ch * 32 + kl) * HID + n];
            g_WcT[(((size_t)h * NCHUNK + ch) * 64 + n) * 32 + c] = f2tf32(v);
        }
    } else {
        int row = b - HEADS * NCHUNK;
        int k = t * 2;
        int ch = k >> 5, kl = k & 31;
        float2 v = *(const float2*)(feat + (size_t)row * IN_DIM + k);
        uint32_t* dst = g_At + ((size_t)ch * NROW_P + row) * 32;
        int c0 = (kl & 3) * 8 + (kl >> 2);
        dst[c0]     = f2tf32(v.x);
        dst[c0 + 8] = f2tf32(v.y);
    }
}

// ---------------- 2. tf32 GEMM + fused src/dst epilogue ----------------------
#define LDI 36
__global__ __launch_bounds__(128) void sgemm_tc(const float* __restrict__ a_heads) {
    __shared__ uint32_t As[2][64 * LDI];
    __shared__ uint32_t Bs[2][64 * LDI];
    __shared__ float s_src[64][2];
    __shared__ float s_dst[64][2];

    int tid = threadIdx.x;
    int warp = tid >> 5, lane = tid & 31;
    int warp_m = warp & 1, warp_n = warp >> 1;
    int gid = lane >> 2, tig = lane & 3;
    int head = blockIdx.x;
    int brow = blockIdx.y * 64;
    int bcol = head * 64;

    int srow = tid >> 3, scol = (tid & 7) * 4;
    const uint32_t* Asrc = g_At + (size_t)brow * 32;
    const uint32_t* Bsrc = g_WcT + (size_t)head * NCHUNK * 64 * 32;

    uint4 va[4], vb[4];
#pragma unroll
    for (int i = 0; i < 4; i++) {
        va[i] = *(const uint4*)(Asrc + (size_t)tid * 4 + i * 512);
        vb[i] = *(const uint4*)(Bsrc + (size_t)tid * 4 + i * 512);
    }
#pragma unroll
    for (int i = 0; i < 4; i++) {
        *(uint4*)&As[0][(srow + i * 16) * LDI + scol] = va[i];
        *(uint4*)&Bs[0][(srow + i * 16) * LDI + scol] = vb[i];
    }
    __syncthreads();

    float c[2][4][4] = {};
    int cur = 0;
    for (int ch = 0; ch < NCHUNK; ch++) {
        bool last = (ch == NCHUNK - 1);
        if (!last) {
            const uint32_t* An = Asrc + (size_t)(ch + 1) * NROW_P * 32;
            const uint32_t* Bn = Bsrc + (size_t)(ch + 1) * 2048;
#pragma unroll
            for (int i = 0; i < 4; i++) {
                va[i] = *(const uint4*)(An + (size_t)tid * 4 + i * 512);
                vb[i] = *(const uint4*)(Bn + (size_t)tid * 4 + i * 512);
            }
        }
        uint32_t alo[2][8], ahi[2][8], bf[4][8];
#pragma unroll
        for (int mt = 0; mt < 2; mt++) {
            int rowA = warp_m * 32 + mt * 16 + gid;
            *(uint4*)&alo[mt][0] = *(uint4*)&As[cur][rowA * LDI + tig * 8];
            *(uint4*)&alo[mt][4] = *(uint4*)&As[cur][rowA * LDI + tig * 8 + 4];
            *(uint4*)&ahi[mt][0] = *(uint4*)&As[cur][(rowA + 8) * LDI + tig * 8];
            *(uint4*)&ahi[mt][4] = *(uint4*)&As[cur][(rowA + 8) * LDI + tig * 8 + 4];
        }
#pragma unroll
        for (int nt = 0; nt < 4; nt++) {
            int rowB = warp_n * 32 + nt * 8 + gid;
            *(uint4*)&bf[nt][0] = *(uint4*)&Bs[cur][rowB * LDI + tig * 8];
            *(uint4*)&bf[nt][4] = *(uint4*)&Bs[cur][rowB * LDI + tig * 8 + 4];
        }
#pragma unroll
        for (int ks = 0; ks < 4; ks++) {
#pragma unroll
            for (int mt = 0; mt < 2; mt++) {
                uint32_t a[4] = {alo[mt][2 * ks], ahi[mt][2 * ks],
                                 alo[mt][2 * ks + 1], ahi[mt][2 * ks + 1]};
#pragma unroll
                for (int nt = 0; nt < 4; nt++) {
                    uint32_t b[2] = {bf[nt][2 * ks], bf[nt][2 * ks + 1]};
                    mma_tf32(c[mt][nt], a, b);
                }
            }
        }
        if (!last) {
            int nxt = cur ^ 1;
#pragma unroll
            for (int i = 0; i < 4; i++) {
                *(uint4*)&As[nxt][(srow + i * 16) * LDI + scol] = va[i];
                *(uint4*)&Bs[nxt][(srow + i * 16) * LDI + scol] = vb[i];
            }
        }
        __syncthreads();
        cur ^= 1;
    }

    const float* av = a_heads + head * (2 * HID);
    float ps[2][2] = {}, pd[2][2] = {};
#pragma unroll
    for (int mt = 0; mt < 2; mt++) {
        int row0 = brow + warp_m * 32 + mt * 16 + gid;
#pragma unroll
        for (int nt = 0; nt < 4; nt++) {
            int cl = warp_n * 32 + nt * 8 + 2 * tig;
            float c0 = c[mt][nt][0], c1 = c[mt][nt][1];
            float c2 = c[mt][nt][2], c3 = c[mt][nt][3];
            float as0 = av[cl], as1 = av[cl + 1];
            float ad0 = av[64 + cl], ad1 = av[64 + cl + 1];
            ps[mt][0] += c0 * as0 + c1 * as1;
            pd[mt][0] += c0 * ad0 + c1 * ad1;
            ps[mt][1] += c2 * as0 + c3 * as1;
            pd[mt][1] += c2 * ad0 + c3 * ad1;
            int colg = bcol + cl;
            if (row0 < N_NODES)
                *(__half2*)(g_Hh + (size_t)row0 * CAT + colg) = __floats2half2_rn(c0, c1);
            if (row0 + 8 < N_NODES)
                *(__half2*)(g_Hh + (size_t)(row0 + 8) * CAT + colg) = __floats2half2_rn(c2, c3);
        }
    }
#pragma unroll
    for (int mt = 0; mt < 2; mt++)
#pragma unroll
        for (int h = 0; h < 2; h++) {
            ps[mt][h] += __shfl_xor_sync(0xffffffffu, ps[mt][h], 1);
            ps[mt][h] += __shfl_xor_sync(0xffffffffu, ps[mt][h], 2);
            pd[mt][h] += __shfl_xor_sync(0xffffffffu, pd[mt][h], 1);
            pd[mt][h] += __shfl_xor_sync(0xffffffffu, pd[mt][h], 2);
        }
    if (tig == 0) {
#pragma unroll
        for (int mt = 0; mt < 2; mt++)
#pragma unroll
            for (int h = 0; h < 2; h++) {
                int rl = warp_m * 32 + mt * 16 + gid + 8 * h;
                s_src[rl][warp_n] = ps[mt][h];
                s_dst[rl][warp_n] = pd[mt][h];
            }
    }
    __syncthreads();
    {
        int rl = tid >> 1, which = tid & 1;
        int row = brow + rl;
        if (row < N_NODES) {
            if (which == 0) g_srcT[row * HEADS + head] = s_src[rl][0] + s_src[rl][1];
            else            g_dstT[row * HEADS + head] = s_dst[rl][0] + s_dst[rl][1];
        }
    }
}

// ---------------- 3. edge build (indices only; binary adjacency) -------------
#define SEGQ 188
__global__ __launch_bounds__(128) void build_edges(const float* __restrict__ adj) {
    int row  = blockIdx.x;
    int tid  = threadIdx.x;
    int w    = tid >> 5, lane = tid & 31;
    __shared__ int   s_bufc[4][128];
    __shared__ int   s_cnt[4];
    __shared__ float s_diag;

    const float4* arow4 = (const float4*)(adj + (size_t)row * N_NODES);
    const int NQ = N_NODES / 4;
    int q0 = w * SEGQ;
    int q1 = min(q0 + SEGQ, NQ);

    int cnt = 0;
    for (int base = q0; base < q1; base += 32) {
        int q = base + lane;
        bool valid = q < q1;
        float a[4] = {0.f, 0.f, 0.f, 0.f};
        int j0 = q * 4;
        if (valid) {
            float4 v = arow4[q];
            a[0] = v.x; a[1] = v.y; a[2] = v.z; a[3] = v.w;
            if (row >= j0 && row < j0 + 4) {
                a[row - j0] += 1.f;               // +I
                s_diag = a[row - j0];             // 1 or 2; single writer
            }
        }
#pragma unroll
        for (int t = 0; t < 4; t++) {
            bool has = valid && (a[t] > 0.f);
            unsigned msk = __ballot_sync(0xffffffffu, has);
            if (has) {
                int pos = cnt + __popc(msk & ((1u << lane) - 1u));
                if (pos < 128) s_bufc[w][pos] = j0 + t;
            }
            cnt += __popc(msk);
        }
    }
    if (lane == 0) s_cnt[w] = cnt;
    __syncthreads();

    int c0 = 0;
#pragma unroll
    for (int t = 0; t < 4; t++) if (t < w) c0 += s_cnt[t];
    int myc = min(s_cnt[w], 128);
    for (int k = lane; k < myc; k += 32) {
        int pos = c0 + k;
        if (pos < MAXDEG) g_cols[row * MAXDEG + pos] = s_bufc[w][k];
    }
    if (tid == 0) {
        int tot = s_cnt[0] + s_cnt[1] + s_cnt[2] + s_cnt[3];
        float dsc = s_diag;
        g_cnt[row]  = tot < MAXDEG ? tot : MAXDEG;
        g_dinv[row] = rsqrtf((float)tot + dsc - 1.f);   // rowsum = nnz + adj_ii
        g_dsc[row]  = dsc;
    }
}

// ---------------- 4. layer-1 sparse attention (launch #4: profiled) ----------
__global__ __launch_bounds__(256) void attn1() {
    int i = blockIdx.x;
    int tid = threadIdx.x;
    int head = tid >> 5, lane = tid & 31;
    __shared__ int   s_cols[MAXDEG];
    __shared__ float s_w[MAXDEG];
    __shared__ float s_p[HEADS][MAXDEG];
    int n = g_cnt[i];
    float di = g_dinv[i];
    float dsc = g_dsc[i];
    for (int k = tid; k < n; k += 256) {
        int j = g_cols[i * MAXDEG + k];
        s_cols[k] = j;
        float wv = di * g_dinv[j];
        s_w[k] = (j == i) ? wv * dsc : wv;
    }
    __syncthreads();

    float si = g_srcT[i * HEADS + head];
    float m = -1e30f;
    for (int k = lane; k < n; k += 32) {
        float e = lrelu(si + __ldg(g_dstT + s_cols[k] * HEADS + head));
        s_p[head][k] = e;
        m = fmaxf(m, e);
    }
#pragma unroll
    for (int o = 16; o; o >>= 1) m = fmaxf(m, __shfl_xor_sync(0xffffffffu, m, o));
    float s = 0.f;
    for (int k = lane; k < n; k += 32) {
        float p = __expf(s_p[head][k] - m);
        s_p[head][k] = p;
        s += p;
    }
#pragma unroll
    for (int o = 16; o; o >>= 1) s += __shfl_xor_sync(0xffffffffu, s, o);
    float inv = 1.f / s;
    __syncwarp();

    const __half2* Hh2 = (const __half2*)g_Hh;
    float2 acc = make_float2(0.f, 0.f);
#pragma unroll 4
    for (int k = 0; k < n; k++) {
        int j = s_cols[k];
        float coef = s_p[head][k] * inv * s_w[k];
        float2 v = __half22float2(__ldg(Hh2 + (size_t)j * (CAT / 2) + head * 32 + lane));
        acc.x = fmaf(coef, v.x, acc.x);
        acc.y = fmaf(coef, v.y, acc.y);
    }
    float2 o = make_float2(elu1(acc.x), elu1(acc.y));
    ((float2*)g_X1)[(size_t)i * (CAT / 2) + head * 32 + lane] = o;
}

// ---------------- 5. H2 = X1 @ W_out, src2/dst2 ------------------------------
__global__ void h2_srcdst(const float* __restrict__ W_out,
                          const float* __restrict__ a_out) {
    int i = blockIdx.x, tid = threadIdx.x;
    __shared__ float sx[CAT];
    __shared__ float sp[16][17];
    __shared__ float sh[NCLASS];
    sx[tid]       = g_X1[(size_t)i * CAT + tid];
    sx[tid + 256] = g_X1[(size_t)i * CAT + tid + 256];
    __syncthreads();
    int c = tid & 15, chunk = tid >> 4;
    float p = 0.f;
    int k0 = chunk * 32;
#pragma unroll 8
    for (int k = k0; k < k0 + 32; k++) p = fmaf(sx[k], __ldg(W_out + k * NCLASS + c), p);
    sp[chunk][c] = p;
    __syncthreads();
    if (tid < NCLASS) {
        float v = 0.f;
#pragma unroll
        for (int q = 0; q < 16; q++) v += sp[q][tid];
        g_H2[i * NCLASS + tid] = v;
        sh[tid] = v;
    }
    __syncthreads();
    if (tid == 0) {
        float s = 0.f, d = 0.f;
#pragma unroll
        for (int cc = 0; cc < NCLASS; cc++) {
            s = fmaf(sh[cc], __ldg(a_out + cc), s);
            d = fmaf(sh[cc], __ldg(a_out + NCLASS + cc), d);
        }
        g_s2[i] = s;
        g_d2[i] = d;
    }
}

// ---------------- 6. layer-2 sparse attention --------------------------------
__global__ void attn2() {
    int w = threadIdx.x >> 5, lane = threadIdx.x & 31;
    int i = blockIdx.x * 4 + w;
    __shared__ int   s_c[4][MAXDEG];
    __shared__ float s_w[4][MAXDEG];
    __shared__ float s_p[4][MAXDEG];
    if (i >= N_NODES) return;
    int n = g_cnt[i];
    float si = g_s2[i];
    float di = g_dinv[i];
    float dsc = g_dsc[i];
    float m = -1e30f;
    for (int k = lane; k < n; k += 32) {
        int j = g_cols[i * MAXDEG + k];
        s_c[w][k] = j;
        float wv = di * g_dinv[j];
        s_w[w][k] = (j == i) ? wv * dsc : wv;
        float e = lrelu(si + g_d2[j]);
        s_p[w][k] = e;
        m = fmaxf(m, e);
    }
#pragma unroll
    for (int o = 16; o; o >>= 1) m = fmaxf(m, __shfl_xor_sync(0xffffffffu, m, o));
    float s = 0.f;
    for (int k = lane; k < n; k += 32) {
        float p = __expf(s_p[w][k] - m);
        s_p[w][k] = p;
        s += p;
    }
#pragma unroll
    for (int o = 16; o; o >>= 1) s += __shfl_xor_sync(0xffffffffu, s, o);
    float inv = 1.f / s;
    __syncwarp();
    if (lane < NCLASS) {
        float acc = 0.f;
        for (int k = 0; k < n; k++) {
            float coef = s_p[w][k] * inv * s_w[w][k];
            acc = fmaf(coef, g_H2[s_c[w][k] * NCLASS + lane], acc);
        }
        g_Z[i * NCLASS + lane] = elu1(elu1(acc));
    }
}

// ---------------- 7. FC head + log_softmax -----------------------------------
__global__ void head_k(const float* __restrict__ FC1,
                       const float* __restrict__ FC2,
                       float* __restrict__ out) {
    int w = threadIdx.x >> 5, lane = threadIdx.x & 31;
    int row = blockIdx.x * 8 + w;
    if (row >= N_NODES) return;
    float z = (lane < NCLASS) ? g_Z[row * NCLASS + lane] : 0.f;
    float y1 = 0.f;
#pragma unroll
    for (int k = 0; k < NCLASS; k++) {
        float zk = __shfl_sync(0xffffffffu, z, k);
        if (lane < NCLASS) y1 = fmaf(zk, __ldg(FC1 + lane * NCLASS + k), y1);
    }
    y1 = elu1(y1);
    float y2 = 0.f;
#pragma unroll
    for (int k = 0; k < NCLASS; k++) {
        float yk = __shfl_sync(0xffffffffu, y1, k);
        if (lane < NCLASS) y2 = fmaf(yk, __ldg(FC2 + lane * NCLASS + k), y2);
    }
    y2 = elu1(y2);
    float v = (lane < NCLASS) ? y2 : -1e30f;
#pragma unroll
    for (int o = 8; o; o >>= 1) v = fmaxf(v, __shfl_xor_sync(0xffffffffu, v, o));
    float e = (lane < NCLASS) ? expf(y2 - v) : 0.f;
    float sum = e;
#pragma unroll
    for (int o = 8; o; o >>= 1) sum += __shfl_xor_sync(0xffffffffu, sum, o);
    if (lane < NCLASS) out[row * NCLASS + lane] = y2 - v - logf(sum);
}

// ---------------- launcher ---------------------------------------------------
extern "C" void kernel_launch(void* const* d_in, const int* in_sizes, int n_in,
                              void* d_out, int out_size) {
    const float* adj     = (const float*)d_in[0];
    const float* feat    = (const float*)d_in[1];
    const float* W_heads = (const float*)d_in[2];
    const float* a_heads = (const float*)d_in[3];
    const float* W_out   = (const float*)d_in[4];
    const float* a_out   = (const float*)d_in[5];
    const float* FC1     = (const float*)d_in[6];
    const float* FC2     = (const float*)d_in[7];
    float* out = (float*)d_out;

    prep_all   <<<HEADS * NCHUNK + N_NODES, 256>>>(W_heads, feat);       // 1
    sgemm_tc   <<<dim3(HEADS, (N_NODES + 63) / 64), 128>>>(a_heads);     // 2
    build_edges<<<N_NODES, 128>>>(adj);                                  // 3
    attn1      <<<N_NODES, 256>>>();                                     // 4 (profiled)
    h2_srcdst  <<<N_NODES, 256>>>(W_out, a_out);                         // 5
    attn2      <<<(N_NODES + 3) / 4, 128>>>();                           // 6
    head_k     <<<(N_NODES + 7) / 8, 256>>>(FC1, FC2, out);              // 7
}

// round 11
// speedup vs baseline: 1.5177x; 1.0224x over previous
#include <cuda_runtime.h>
#include <cuda_fp16.h>
#include <math.h>
#include <stdint.h>

#define N_NODES 3000
#define NROW_P  3008
#define IN_DIM  512
#define HID     64
#define HEADS   8
#define CAT     512
#define NCLASS  16
#define MAXDEG  256
#define ALPHA   0.2f
#define NCHUNK  16        // IN_DIM/32

// ---------------- scratch -----------------------------------------------------
__device__ float    g_dinv[N_NODES];
__device__ float    g_dsc [N_NODES];                    // diagonal a1 value (1 or 2)
__device__ int      g_cnt [N_NODES];
__device__ int      g_cols[N_NODES * MAXDEG];
__device__ uint32_t g_At  [NCHUNK * NROW_P * 32];       // tf32 A, k-interleaved
__device__ uint32_t g_WcT [HEADS * NCHUNK * 64 * 32];   // tf32 W, transposed+interleaved
__device__ __half   g_Hh  [N_NODES * CAT];
__device__ float    g_srcT[N_NODES * HEADS];
__device__ float    g_dstT[N_NODES * HEADS];
__device__ float    g_X1  [N_NODES * CAT];
__device__ float    g_H2  [N_NODES * NCLASS];
__device__ float    g_s2  [N_NODES];
__device__ float    g_d2  [N_NODES];
__device__ float    g_Z   [N_NODES * NCLASS];

__device__ __forceinline__ float elu1(float x) { return x > 0.f ? x : expm1f(x); }
__device__ __forceinline__ float lrelu(float x){ return x >= 0.f ? x : ALPHA * x; }
__device__ __forceinline__ uint32_t f2tf32(float f) {
    uint32_t u; asm("cvt.rna.tf32.f32 %0, %1;" : "=r"(u) : "f"(f)); return u;
}
__device__ __forceinline__ void mma_tf32(float* c, const uint32_t* a, const uint32_t* b) {
    asm volatile(
        "mma.sync.aligned.m16n8k8.row.col.f32.tf32.tf32.f32 "
        "{%0,%1,%2,%3}, {%4,%5,%6,%7}, {%8,%9}, {%0,%1,%2,%3};\n"
        : "+f"(c[0]), "+f"(c[1]), "+f"(c[2]), "+f"(c[3])
        : "r"(a[0]), "r"(a[1]), "r"(a[2]), "r"(a[3]), "r"(b[0]), "r"(b[1]));
}

// ---------------- 1. fused prep: pack_w (blocks 0..127) + prep_A (rest) ------
__global__ __launch_bounds__(256) void prep_all(const float* __restrict__ W_heads,
                                                const float* __restrict__ feat) {
    int b = blockIdx.x;
    int t = threadIdx.x;
    if (b < HEADS * NCHUNK) {
        int h = b >> 4, ch = b & 15;
#pragma unroll
        for (int i = 0; i < 8; i++) {
            int idx = t * 8 + i;
            int n = idx >> 5, c = idx & 31;
            int kl = (c & 7) * 4 + (c >> 3);
            float v = W_heads[((size_t)h * IN_DIM + ch * 32 + kl) * HID + n];
            g_WcT[(((size_t)h * NCHUNK + ch) * 64 + n) * 32 + c] = f2tf32(v);
        }
    } else {
        int row = b - HEADS * NCHUNK;
        int k = t * 2;
        int ch = k >> 5, kl = k & 31;
        float2 v = *(const float2*)(feat + (size_t)row * IN_DIM + k);
        uint32_t* dst = g_At + ((size_t)ch * NROW_P + row) * 32;
        int c0 = (kl & 3) * 8 + (kl >> 2);
        dst[c0]     = f2tf32(v.x);
        dst[c0 + 8] = f2tf32(v.y);
    }
}

// ---------------- 2. tf32 GEMM + fused src/dst epilogue ----------------------
#define LDI 36
__global__ __launch_bounds__(128) void sgemm_tc(const float* __restrict__ a_heads) {
    __shared__ uint32_t As[2][64 * LDI];
    __shared__ uint32_t Bs[2][64 * LDI];
    __shared__ float s_src[64][2];
    __shared__ float s_dst[64][2];

    int tid = threadIdx.x;
    int warp = tid >> 5, lane = tid & 31;
    int warp_m = warp & 1, warp_n = warp >> 1;
    int gid = lane >> 2, tig = lane & 3;
    int head = blockIdx.x;
    int brow = blockIdx.y * 64;
    int bcol = head * 64;

    int srow = tid >> 3, scol = (tid & 7) * 4;
    const uint32_t* Asrc = g_At + (size_t)brow * 32;
    const uint32_t* Bsrc = g_WcT + (size_t)head * NCHUNK * 64 * 32;

    uint4 va[4], vb[4];
#pragma unroll
    for (int i = 0; i < 4; i++) {
        va[i] = *(const uint4*)(Asrc + (size_t)tid * 4 + i * 512);
        vb[i] = *(const uint4*)(Bsrc + (size_t)tid * 4 + i * 512);
    }
#pragma unroll
    for (int i = 0; i < 4; i++) {
        *(uint4*)&As[0][(srow + i * 16) * LDI + scol] = va[i];
        *(uint4*)&Bs[0][(srow + i * 16) * LDI + scol] = vb[i];
    }
    __syncthreads();

    float c[2][4][4] = {};
    int cur = 0;
    for (int ch = 0; ch < NCHUNK; ch++) {
        bool last = (ch == NCHUNK - 1);
        if (!last) {
            const uint32_t* An = Asrc + (size_t)(ch + 1) * NROW_P * 32;
            const uint32_t* Bn = Bsrc + (size_t)(ch + 1) * 2048;
#pragma unroll
            for (int i = 0; i < 4; i++) {
                va[i] = *(const uint4*)(An + (size_t)tid * 4 + i * 512);
                vb[i] = *(const uint4*)(Bn + (size_t)tid * 4 + i * 512);
            }
        }
        uint32_t alo[2][8], ahi[2][8], bf[4][8];
#pragma unroll
        for (int mt = 0; mt < 2; mt++) {
            int rowA = warp_m * 32 + mt * 16 + gid;
            *(uint4*)&alo[mt][0] = *(uint4*)&As[cur][rowA * LDI + tig * 8];
            *(uint4*)&alo[mt][4] = *(uint4*)&As[cur][rowA * LDI + tig * 8 + 4];
            *(uint4*)&ahi[mt][0] = *(uint4*)&As[cur][(rowA + 8) * LDI + tig * 8];
            *(uint4*)&ahi[mt][4] = *(uint4*)&As[cur][(rowA + 8) * LDI + tig * 8 + 4];
        }
#pragma unroll
        for (int nt = 0; nt < 4; nt++) {
            int rowB = warp_n * 32 + nt * 8 + gid;
            *(uint4*)&bf[nt][0] = *(uint4*)&Bs[cur][rowB * LDI + tig * 8];
            *(uint4*)&bf[nt][4] = *(uint4*)&Bs[cur][rowB * LDI + tig * 8 + 4];
        }
#pragma unroll
        for (int ks = 0; ks < 4; ks++) {
#pragma unroll
            for (int mt = 0; mt < 2; mt++) {
                uint32_t a[4] = {alo[mt][2 * ks], ahi[mt][2 * ks],
                                 alo[mt][2 * ks + 1], ahi[mt][2 * ks + 1]};
#pragma unroll
                for (int nt = 0; nt < 4; nt++) {
                    uint32_t b[2] = {bf[nt][2 * ks], bf[nt][2 * ks + 1]};
                    mma_tf32(c[mt][nt], a, b);
                }
            }
        }
        if (!last) {
            int nxt = cur ^ 1;
#pragma unroll
            for (int i = 0; i < 4; i++) {
                *(uint4*)&As[nxt][(srow + i * 16) * LDI + scol] = va[i];
                *(uint4*)&Bs[nxt][(srow + i * 16) * LDI + scol] = vb[i];
            }
        }
        __syncthreads();
        cur ^= 1;
    }

    const float* av = a_heads + head * (2 * HID);
    float ps[2][2] = {}, pd[2][2] = {};
#pragma unroll
    for (int mt = 0; mt < 2; mt++) {
        int row0 = brow + warp_m * 32 + mt * 16 + gid;
#pragma unroll
        for (int nt = 0; nt < 4; nt++) {
            int cl = warp_n * 32 + nt * 8 + 2 * tig;
            float c0 = c[mt][nt][0], c1 = c[mt][nt][1];
            float c2 = c[mt][nt][2], c3 = c[mt][nt][3];
            float as0 = av[cl], as1 = av[cl + 1];
            float ad0 = av[64 + cl], ad1 = av[64 + cl + 1];
            ps[mt][0] += c0 * as0 + c1 * as1;
            pd[mt][0] += c0 * ad0 + c1 * ad1;
            ps[mt][1] += c2 * as0 + c3 * as1;
            pd[mt][1] += c2 * ad0 + c3 * ad1;
            int colg = bcol + cl;
            if (row0 < N_NODES)
                *(__half2*)(g_Hh + (size_t)row0 * CAT + colg) = __floats2half2_rn(c0, c1);
            if (row0 + 8 < N_NODES)
                *(__half2*)(g_Hh + (size_t)(row0 + 8) * CAT + colg) = __floats2half2_rn(c2, c3);
        }
    }
#pragma unroll
    for (int mt = 0; mt < 2; mt++)
#pragma unroll
        for (int h = 0; h < 2; h++) {
            ps[mt][h] += __shfl_xor_sync(0xffffffffu, ps[mt][h], 1);
            ps[mt][h] += __shfl_xor_sync(0xffffffffu, ps[mt][h], 2);
            pd[mt][h] += __shfl_xor_sync(0xffffffffu, pd[mt][h], 1);
            pd[mt][h] += __shfl_xor_sync(0xffffffffu, pd[mt][h], 2);
        }
    if (tig == 0) {
#pragma unroll
        for (int mt = 0; mt < 2; mt++)
#pragma unroll
            for (int h = 0; h < 2; h++) {
                int rl = warp_m * 32 + mt * 16 + gid + 8 * h;
                s_src[rl][warp_n] = ps[mt][h];
                s_dst[rl][warp_n] = pd[mt][h];
            }
    }
    __syncthreads();
    {
        int rl = tid >> 1, which = tid & 1;
        int row = brow + rl;
        if (row < N_NODES) {
            if (which == 0) g_srcT[row * HEADS + head] = s_src[rl][0] + s_src[rl][1];
            else            g_dstT[row * HEADS + head] = s_dst[rl][0] + s_dst[rl][1];
        }
    }
}

// ---------------- 3. edge build (indices only; binary adjacency) -------------
#define SEGQ 188
__global__ __launch_bounds__(128) void build_edges(const float* __restrict__ adj) {
    int row  = blockIdx.x;
    int tid  = threadIdx.x;
    int w    = tid >> 5, lane = tid & 31;
    __shared__ int   s_bufc[4][128];
    __shared__ int   s_cnt[4];
    __shared__ float s_diag;

    const float4* arow4 = (const float4*)(adj + (size_t)row * N_NODES);
    const int NQ = N_NODES / 4;
    int q0 = w * SEGQ;
    int q1 = min(q0 + SEGQ, NQ);

    int cnt = 0;
    for (int base = q0; base < q1; base += 32) {
        int q = base + lane;
        bool valid = q < q1;
        float a[4] = {0.f, 0.f, 0.f, 0.f};
        int j0 = q * 4;
        if (valid) {
            float4 v = arow4[q];
            a[0] = v.x; a[1] = v.y; a[2] = v.z; a[3] = v.w;
            if (row >= j0 && row < j0 + 4) {
                a[row - j0] += 1.f;
                s_diag = a[row - j0];
            }
        }
#pragma unroll
        for (int t = 0; t < 4; t++) {
            bool has = valid && (a[t] > 0.f);
            unsigned msk = __ballot_sync(0xffffffffu, has);
            if (has) {
                int pos = cnt + __popc(msk & ((1u << lane) - 1u));
                if (pos < 128) s_bufc[w][pos] = j0 + t;
            }
            cnt += __popc(msk);
        }
    }
    if (lane == 0) s_cnt[w] = cnt;
    __syncthreads();

    int c0 = 0;
#pragma unroll
    for (int t = 0; t < 4; t++) if (t < w) c0 += s_cnt[t];
    int myc = min(s_cnt[w], 128);
    for (int k = lane; k < myc; k += 32) {
        int pos = c0 + k;
        if (pos < MAXDEG) g_cols[row * MAXDEG + pos] = s_bufc[w][k];
    }
    if (tid == 0) {
        int tot = s_cnt[0] + s_cnt[1] + s_cnt[2] + s_cnt[3];
        float dsc = s_diag;
        g_cnt[row]  = tot < MAXDEG ? tot : MAXDEG;
        g_dinv[row] = rsqrtf((float)tot + dsc - 1.f);
        g_dsc[row]  = dsc;
    }
}

// ---------------- 4. layer-1 attention: vectorized 4-edge gather -------------
__global__ __launch_bounds__(256) void attn1() {
    int i = blockIdx.x;
    int tid = threadIdx.x;
    int head = tid >> 5, lane = tid & 31;
    __shared__ int   s_cols[MAXDEG];
    __shared__ float s_w[MAXDEG];
    __shared__ float s_p[HEADS][MAXDEG];
    int n = g_cnt[i];
    int n4 = (n + 3) & ~3;
    float di = g_dinv[i];
    float dsc = g_dsc[i];
    for (int k = tid; k < n4; k += 256) {
        if (k < n) {
            int j = g_cols[i * MAXDEG + k];
            s_cols[k] = j;
            float wv = di * g_dinv[j];
            s_w[k] = (j == i) ? wv * dsc : wv;
        } else {
            s_cols[k] = 0;
        }
    }
    __syncthreads();

    float si = g_srcT[i * HEADS + head];
    float m = -1e30f;
    for (int k = lane; k < n; k += 32) {
        float e = lrelu(si + __ldg(g_dstT + s_cols[k] * HEADS + head));
        s_p[head][k] = e;
        m = fmaxf(m, e);
    }
#pragma unroll
    for (int o = 16; o; o >>= 1) m = fmaxf(m, __shfl_xor_sync(0xffffffffu, m, o));
    float s = 0.f;
    for (int k = lane; k < n; k += 32) {
        float p = __expf(s_p[head][k] - m);
        s_p[head][k] = p;
        s += p;
    }
#pragma unroll
    for (int o = 16; o; o >>= 1) s += __shfl_xor_sync(0xffffffffu, s, o);
    float inv = 1.f / s;
    // finalize coef in smem (padded entries = 0)
    for (int k = lane; k < n4; k += 32)
        s_p[head][k] = (k < n) ? s_p[head][k] * inv * s_w[k] : 0.f;
    __syncwarp();

    // gather: lane = (e,f); 4 edges per iteration, 8 fp16 feats per lane
    int e = lane >> 3, f = lane & 7;
    const __half* Hbase = g_Hh + head * HID + f * 8;
    float acc[8] = {};
    for (int k = 0; k < n4; k += 4) {
        int edge = k + e;
        float coef = s_p[head][edge];
        int j = s_cols[edge];
        uint4 raw = *(const uint4*)(Hbase + (size_t)j * CAT);
        const __half2* hx = (const __half2*)&raw;
        float2 v0 = __half22float2(hx[0]);
        float2 v1 = __half22float2(hx[1]);
        float2 v2 = __half22float2(hx[2]);
        float2 v3 = __half22float2(hx[3]);
        acc[0] = fmaf(coef, v0.x, acc[0]);
        acc[1] = fmaf(coef, v0.y, acc[1]);
        acc[2] = fmaf(coef, v1.x, acc[2]);
        acc[3] = fmaf(coef, v1.y, acc[3]);
        acc[4] = fmaf(coef, v2.x, acc[4]);
        acc[5] = fmaf(coef, v2.y, acc[5]);
        acc[6] = fmaf(coef, v3.x, acc[6]);
        acc[7] = fmaf(coef, v3.y, acc[7]);
    }
#pragma unroll
    for (int t = 0; t < 8; t++) {
        acc[t] += __shfl_xor_sync(0xffffffffu, acc[t], 8);
        acc[t] += __shfl_xor_sync(0xffffffffu, acc[t], 16);
    }
    if (e == 0) {
        float4 o0 = make_float4(elu1(acc[0]), elu1(acc[1]), elu1(acc[2]), elu1(acc[3]));
        float4 o1 = make_float4(elu1(acc[4]), elu1(acc[5]), elu1(acc[6]), elu1(acc[7]));
        float* dst = g_X1 + (size_t)i * CAT + head * HID + f * 8;
        *(float4*)(dst)     = o0;
        *(float4*)(dst + 4) = o1;
    }
}

// ---------------- 5. H2 + src2/dst2: 4 rows/block, W_out in smem -------------
__global__ __launch_bounds__(256) void h2_srcdst(const float* __restrict__ W_out,
                                                 const float* __restrict__ a_out) {
    int i0 = blockIdx.x * 4;
    int tid = threadIdx.x;
    __shared__ float sW[IN_DIM * NCLASS];      // 32KB
    __shared__ float sx[4][IN_DIM];            // 8KB
    __shared__ float sp[4][2][NCLASS];
    __shared__ float sh[4][NCLASS];
#pragma unroll
    for (int q = 0; q < 8; q++)
        *(float4*)&sW[tid * 4 + q * 1024] = *(const float4*)(W_out + tid * 4 + q * 1024);
#pragma unroll
    for (int q = 0; q < 2; q++) {
        int idx = tid * 4 + q * 1024;           // 0..2047
        *(float4*)&sx[idx >> 9][idx & 511] = *(const float4*)(g_X1 + (size_t)i0 * IN_DIM + idx);
    }
    __syncthreads();

    int warp = tid >> 5, lane = tid & 31;
    int r = warp >> 1, half = warp & 1;
    int c = lane & 15, sub = lane >> 4;
    float p = 0.f;
    int kbase = half * 256;
#pragma unroll 8
    for (int kk = 0; kk < 128; kk++) {
        int k = kbase + kk * 2 + sub;           // parity split: conflict-free sW
        p = fmaf(sx[r][k], sW[k * NCLASS + c], p);
    }
    p += __shfl_xor_sync(0xffffffffu, p, 16);
    if (sub == 0) sp[r][half][c] = p;
    __syncthreads();
    if (tid < 64) {
        int rr = tid >> 4, cc = tid & 15;
        float v = sp[rr][0][cc] + sp[rr][1][cc];
        g_H2[(i0 + rr) * NCLASS + cc] = v;
        sh[rr][cc] = v;
    }
    __syncthreads();
    if (tid < 8) {
        int rr = tid >> 1, which = tid & 1;
        const float* a = a_out + which * NCLASS;
        float v = 0.f;
#pragma unroll
        for (int cc = 0; cc < NCLASS; cc++) v = fmaf(sh[rr][cc], __ldg(a + cc), v);
        if (which == 0) g_s2[i0 + rr] = v;
        else            g_d2[i0 + rr] = v;
    }
}

// ---------------- 6. layer-2 sparse attention --------------------------------
__global__ void attn2() {
    int w = threadIdx.x >> 5, lane = threadIdx.x & 31;
    int i = blockIdx.x * 4 + w;
    __shared__ int   s_c[4][MAXDEG];
    __shared__ float s_w[4][MAXDEG];
    __shared__ float s_p[4][MAXDEG];
    if (i >= N_NODES) return;
    int n = g_cnt[i];
    float si = g_s2[i];
    float di = g_dinv[i];
    float dsc = g_dsc[i];
    float m = -1e30f;
    for (int k = lane; k < n; k += 32) {
        int j = g_cols[i * MAXDEG + k];
        s_c[w][k] = j;
        float wv = di * g_dinv[j];
        s_w[w][k] = (j == i) ? wv * dsc : wv;
        float e = lrelu(si + g_d2[j]);
        s_p[w][k] = e;
        m = fmaxf(m, e);
    }
#pragma unroll
    for (int o = 16; o; o >>= 1) m = fmaxf(m, __shfl_xor_sync(0xffffffffu, m, o));
    float s = 0.f;
    for (int k = lane; k < n; k += 32) {
        float p = __expf(s_p[w][k] - m);
        s_p[w][k] = p;
        s += p;
    }
#pragma unroll
    for (int o = 16; o; o >>= 1) s += __shfl_xor_sync(0xffffffffu, s, o);
    float inv = 1.f / s;
    __syncwarp();
    if (lane < NCLASS) {
        float acc = 0.f;
        for (int k = 0; k < n; k++) {
            float coef = s_p[w][k] * inv * s_w[w][k];
            acc = fmaf(coef, g_H2[s_c[w][k] * NCLASS + lane], acc);
        }
        g_Z[i * NCLASS + lane] = elu1(elu1(acc));
    }
}

// ---------------- 7. FC head + log_softmax -----------------------------------
__global__ void head_k(const float* __restrict__ FC1,
                       const float* __restrict__ FC2,
                       float* __restrict__ out) {
    int w = threadIdx.x >> 5, lane = threadIdx.x & 31;
    int row = blockIdx.x * 8 + w;
    if (row >= N_NODES) return;
    float z = (lane < NCLASS) ? g_Z[row * NCLASS + lane] : 0.f;
    float y1 = 0.f;
#pragma unroll
    for (int k = 0; k < NCLASS; k++) {
        float zk = __shfl_sync(0xffffffffu, z, k);
        if (lane < NCLASS) y1 = fmaf(zk, __ldg(FC1 + lane * NCLASS + k), y1);
    }
    y1 = elu1(y1);
    float y2 = 0.f;
#pragma unroll
    for (int k = 0; k < NCLASS; k++) {
        float yk = __shfl_sync(0xffffffffu, y1, k);
        if (lane < NCLASS) y2 = fmaf(yk, __ldg(FC2 + lane * NCLASS + k), y2);
    }
    y2 = elu1(y2);
    float v = (lane < NCLASS) ? y2 : -1e30f;
#pragma unroll
    for (int o = 8; o; o >>= 1) v = fmaxf(v, __shfl_xor_sync(0xffffffffu, v, o));
    float e = (lane < NCLASS) ? expf(y2 - v) : 0.f;
    float sum = e;
#pragma unroll
    for (int o = 8; o; o >>= 1) sum += __shfl_xor_sync(0xffffffffu, sum, o);
    if (lane < NCLASS) out[row * NCLASS + lane] = y2 - v - logf(sum);
}

// ---------------- launcher ---------------------------------------------------
extern "C" void kernel_launch(void* const* d_in, const int* in_sizes, int n_in,
                              void* d_out, int out_size) {
    const float* adj     = (const float*)d_in[0];
    const float* feat    = (const float*)d_in[1];
    const float* W_heads = (const float*)d_in[2];
    const float* a_heads = (const float*)d_in[3];
    const float* W_out   = (const float*)d_in[4];
    const float* a_out   = (const float*)d_in[5];
    const float* FC1     = (const float*)d_in[6];
    const float* FC2     = (const float*)d_in[7];
    float* out = (float*)d_out;

    prep_all   <<<HEADS * NCHUNK + N_NODES, 256>>>(W_heads, feat);       // 1
    sgemm_tc   <<<dim3(HEADS, (N_NODES + 63) / 64), 128>>>(a_heads);     // 2
    build_edges<<<N_NODES, 128>>>(adj);                                  // 3
    attn1      <<<N_NODES, 256>>>();                                     // 4 (profiled)
    h2_srcdst  <<<N_NODES / 4, 256>>>(W_out, a_out);                     // 5
    attn2      <<<(N_NODES + 3) / 4, 128>>>();                           // 6
    head_k     <<<(N_NODES + 7) / 8, 256>>>(FC1, FC2, out);              // 7
}